// round 15
// baseline (speedup 1.0000x reference)
#include <cuda_runtime.h>
#include <cstdint>
#include <math.h>

#define BB 8192

__device__ __forceinline__ float tf32r(float x) {
    uint32_t u;
    asm("cvt.rna.tf32.f32 %0, %1;" : "=r"(u) : "f"(x));
    return __uint_as_float(u);
}

__device__ __forceinline__ void mma_tf32(float c[4],
                                         uint32_t a0, uint32_t a1, uint32_t a2, uint32_t a3,
                                         uint32_t b0, uint32_t b1) {
    asm volatile(
        "mma.sync.aligned.m16n8k8.row.col.f32.tf32.tf32.f32 "
        "{%0,%1,%2,%3}, {%4,%5,%6,%7}, {%8,%9}, {%0,%1,%2,%3};"
        : "+f"(c[0]), "+f"(c[1]), "+f"(c[2]), "+f"(c[3])
        : "r"(a0), "r"(a1), "r"(a2), "r"(a3), "r"(b0), "r"(b1));
}

__device__ __forceinline__ void ldsm_x4(uint32_t& r0, uint32_t& r1, uint32_t& r2, uint32_t& r3,
                                        uint32_t addr) {
    asm volatile("ldmatrix.sync.aligned.m8n8.x4.shared.b16 {%0,%1,%2,%3}, [%4];"
                 : "=r"(r0), "=r"(r1), "=r"(r2), "=r"(r3) : "r"(addr));
}

__device__ __forceinline__ uint32_t smem_u32(const void* p) {
    return (uint32_t)__cvta_generic_to_shared(p);
}

__device__ __forceinline__ void cp_async16(uint32_t dst, const void* src) {
    asm volatile("cp.async.cg.shared.global [%0], [%1], 16;" :: "r"(dst), "l"(src));
}
__device__ __forceinline__ void cp_async16z(uint32_t dst, const void* src, bool valid) {
    int sz = valid ? 16 : 0;
    asm volatile("cp.async.cg.shared.global [%0], [%1], 16, %2;"
                 :: "r"(dst), "l"(src), "r"(sz));
}
__device__ __forceinline__ void cp_commit() {
    asm volatile("cp.async.commit_group;");
}
template<int N>
__device__ __forceinline__ void cp_wait() {
    asm volatile("cp.async.wait_group %0;" :: "n"(N));
}

// ---------------- scratch ----------------------------------------------------
// g_buf1: Y [0,B*1536) | Tt [B*1536,B*4608) (layout [b][g][96n]) | Wt | CW* | CWC*
__device__ float g_A[96 * 96];
__device__ float g_Aq[128 * 96];                 // tf32-rounded, rows 96..127 zero
__device__ float g_buf1[(size_t)BB * 6144];
__device__ float g_buf2[(size_t)BB * 3072];

constexpr size_t WT_OFF   = (size_t)BB * 4608;
constexpr size_t CW1_OFF  = WT_OFF + 393216;
constexpr size_t CW2_OFF  = CW1_OFF + 14336;
constexpr size_t CW3_OFF  = CW2_OFF + 40960;
constexpr size_t CWC1_OFF = CW3_OFF + 98304;
constexpr size_t CWC2_OFF = CWC1_OFF + 16384;

// ---------------- build dense normalized adjacency ---------------------------
__global__ void k_build_adj(const int* __restrict__ ei, int ne) {
    __shared__ float deg[96];
    __shared__ float dinv[96];
    int t = threadIdx.x;
    if (t < 96) deg[t] = 0.f;
    for (int i = t; i < 9216; i += 256) g_A[i] = 0.f;
    __syncthreads();
    for (int e = t; e < ne; e += 256) atomicAdd(&deg[ei[e]], 1.0f);
    if (t < 96) atomicAdd(&deg[t], 1.0f);
    __syncthreads();
    if (t < 96) dinv[t] = 1.0f / sqrtf(fmaxf(deg[t], 1e-12f));
    __syncthreads();
    for (int e = t; e < ne; e += 256) {
        int r = ei[e], c = ei[ne + e];
        atomicAdd(&g_A[r * 96 + c], dinv[r] * dinv[c]);
    }
    if (t < 96) atomicAdd(&g_A[t * 96 + t], dinv[t] * dinv[t]);
}

__global__ void k_prea() {
    int i = blockIdx.x * 256 + threadIdx.x;
    if (i < 128 * 96) g_Aq[i] = (i < 9216) ? tf32r(g_A[i]) : 0.f;
}

// ---------------- one-time weight prep ---------------------------------------
__global__ void k_trW(const float* __restrict__ W) {
    float* Wt = g_buf1 + WT_OFF;
    int i = blockIdx.x * 256 + threadIdx.x;
    if (i < 393216) {
        int m = i / 3072, kn = i % 3072;
        int p = kn >> 8, c = kn & 255;
        Wt[i] = tf32r(W[(size_t)(c * 12 + p) * 128 + m]);
    }
}

__global__ void k_prew(const float* __restrict__ w1, const float* __restrict__ w2,
                       const float* __restrict__ w3, const float* __restrict__ c1,
                       const float* __restrict__ c2) {
    int i = blockIdx.x * 256 + threadIdx.x;
    if (i < 14336) {
        int o = i / 224, r = i % 224, ic = r / 7, kk = r % 7;
        g_buf1[CW1_OFF + o * 224 + kk * 32 + ic] = tf32r(w1[i]);
    }
    if (i < 40960) {
        int o = i / 320, r = i % 320, ic = r / 5, kk = r % 5;
        g_buf1[CW2_OFF + o * 320 + kk * 64 + ic] = tf32r(w2[i]);
    }
    if (i < 98304) {
        int o = i / 384, r = i % 384, ic = r / 3, kk = r % 3;
        g_buf1[CW3_OFF + o * 384 + kk * 128 + ic] = tf32r(w3[i]);
    }
    if (i < 16384) {
        int m = i >> 7, k = i & 127;
        g_buf1[CWC1_OFF + i] = tf32r(c1[(size_t)k * 128 + m]);
    }
    if (i < 32768) {
        int m = i >> 7, k = i & 127;
        g_buf1[CWC2_OFF + i] = (m < 210) ? tf32r(c2[(size_t)k * 210 + m]) : 0.f;
    }
}

// ---------------- gcnA via mma: Y[n,(b,c)] = A@Xq ----------------------------
__global__ void __launch_bounds__(256, 3) k_gcnAmma(const float* __restrict__ src) {
    __shared__ float sA[128 * 36];
    __shared__ float sB[64 * 36];
    int t = threadIdx.x;
    int warp = t >> 5, lane = t & 31;
    int g = lane >> 2, tg = lane & 3;
    long n0 = (long)blockIdx.x * 64;
    float acc[8][4] = {};

    int atile = lane >> 3;
    int arow = warp * 16 + (lane & 7) + ((atile & 1) << 3);
    uint32_t aaddr = smem_u32(sA) + (uint32_t)(arow * 36 + (atile >> 1) * 4) * 4u;
    int brow = ((lane >> 4) << 3) + (lane & 7);
    uint32_t baddr = smem_u32(sB) + (uint32_t)(brow * 36 + ((lane >> 3) & 1) * 4) * 4u;

    for (int k0 = 0; k0 < 96; k0 += 32) {
        __syncthreads();
        for (int i = t; i < 128 * 8; i += 256) {
            int m = i >> 3, k4 = i & 7;
            *(float4*)&sA[m * 36 + k4 * 4] = *(const float4*)&g_Aq[m * 96 + k0 + k4 * 4];
        }
        for (int i = t; i < 64 * 8; i += 256) {   // float4: src contiguous in k
            int n = i >> 3, q = i & 7;
            long col = n0 + n;
            int b = (int)(col >> 4), c = (int)(col & 15);
            float4 v = *(const float4*)&src[(size_t)b * 1536 + c * 96 + k0 + q * 4];
            v.x = tf32r(v.x); v.y = tf32r(v.y); v.z = tf32r(v.z); v.w = tf32r(v.w);
            *(float4*)&sB[n * 36 + q * 4] = v;
        }
        __syncthreads();
        #pragma unroll
        for (int ks = 0; ks < 4; ks++) {
            int kb = ks * 8;
            uint32_t a0, a1, a2, a3;
            ldsm_x4(a0, a1, a2, a3, aaddr + kb * 4);
            #pragma unroll
            for (int p = 0; p < 4; p++) {
                uint32_t b0, b1, b2, b3;
                ldsm_x4(b0, b1, b2, b3, baddr + (p * 16 * 36 + kb) * 4);
                mma_tf32(acc[2 * p],     a0, a1, a2, a3, b0, b1);
                mma_tf32(acc[2 * p + 1], a0, a1, a2, a3, b2, b3);
            }
        }
    }
    int m0 = warp * 16 + g, m1 = m0 + 8;
    if (m0 < 96) {
        #pragma unroll
        for (int j = 0; j < 8; j++) {
            long nc = n0 + j * 8 + 2 * tg;
            int b = (int)(nc >> 4), c = (int)(nc & 15);
            float* yb = g_buf1 + (size_t)b * 1536;
            yb[m0 * 16 + c]     = acc[j][0];
            yb[m0 * 16 + c + 1] = acc[j][1];
            yb[m1 * 16 + c]     = acc[j][2];
            yb[m1 * 16 + c + 1] = acc[j][3];
        }
    }
}

// ---------------- gcnB via fused 2-stage mma (T stored transposed+rounded) ---
__global__ void __launch_bounds__(256, 3) k_gcnBmma(const float* __restrict__ W1,
                                                    const float* __restrict__ b1,
                                                    const float* __restrict__ W2) {
    extern __shared__ float sm[];
    float* sW1 = sm;                  // [64 f][20]
    float* sW2 = sW1 + 64 * 20;       // [32 g][68]
    float* sY  = sW2 + 32 * 68;       // [128 row][20]
    float* sH  = sY + 128 * 20;       // [128 row][68]
    float* sB1 = sH + 128 * 68;       // [64]
    int t = threadIdx.x;
    int warp = t >> 5, lane = t & 31;
    int g = lane >> 2, tg = lane & 3;
    size_t row0 = (size_t)blockIdx.x * 128;

    for (int i = t; i < 1024; i += 256) {
        int c = i >> 6, f = i & 63;
        sW1[f * 20 + c] = tf32r(W1[i]);
    }
    for (int i = t; i < 2048; i += 256) {
        int f = i >> 5, gg = i & 31;
        sW2[gg * 68 + f] = tf32r(W2[i]);
    }
    if (t < 64) sB1[t] = b1[t];
    for (int i = t; i < 128 * 4; i += 256) {
        int r = i >> 2, c4 = i & 3;
        float4 v = *(const float4*)&g_buf1[(row0 + r) * 16 + c4 * 4];
        v.x = tf32r(v.x); v.y = tf32r(v.y); v.z = tf32r(v.z); v.w = tf32r(v.w);
        *(float4*)&sY[r * 20 + c4 * 4] = v;
    }
    __syncthreads();

    {   // stage 1
        int wm = warp & 3, wn = warp >> 2;
        int atile = lane >> 3;
        int arow = wm * 16 + (lane & 7) + ((atile & 1) << 3);
        uint32_t aaddr = smem_u32(sW1) + (uint32_t)(arow * 20 + (atile >> 1) * 4) * 4u;
        int brow = wn * 64 + ((lane >> 4) << 3) + (lane & 7);
        uint32_t baddr = smem_u32(sY) + (uint32_t)(brow * 20 + ((lane >> 3) & 1) * 4) * 4u;

        float acc[8][4] = {};
        #pragma unroll
        for (int ks = 0; ks < 2; ks++) {
            int kb = ks * 8;
            uint32_t a0, a1, a2, a3;
            ldsm_x4(a0, a1, a2, a3, aaddr + kb * 4);
            #pragma unroll
            for (int p = 0; p < 4; p++) {
                uint32_t b0, b1, b2, b3;
                ldsm_x4(b0, b1, b2, b3, baddr + (p * 16 * 20 + kb) * 4);
                mma_tf32(acc[2 * p],     a0, a1, a2, a3, b0, b1);
                mma_tf32(acc[2 * p + 1], a0, a1, a2, a3, b2, b3);
            }
        }
        int m0 = wm * 16 + g, m1 = m0 + 8;
        float bi0 = sB1[m0], bi1 = sB1[m1];
        #pragma unroll
        for (int j = 0; j < 8; j++) {
            int r = wn * 64 + j * 8 + 2 * tg;
            sH[r * 68 + m0]       = tf32r(fmaxf(acc[j][0] + bi0, 0.f));
            sH[(r + 1) * 68 + m0] = tf32r(fmaxf(acc[j][1] + bi0, 0.f));
            sH[r * 68 + m1]       = tf32r(fmaxf(acc[j][2] + bi1, 0.f));
            sH[(r + 1) * 68 + m1] = tf32r(fmaxf(acc[j][3] + bi1, 0.f));
        }
    }
    __syncthreads();

    {   // stage 2: store Tt[b][g][96n], pre-rounded
        int wm = warp & 1, wn = warp >> 1;
        int atile = lane >> 3;
        int arow = wm * 16 + (lane & 7) + ((atile & 1) << 3);
        uint32_t aaddr = smem_u32(sW2) + (uint32_t)(arow * 68 + (atile >> 1) * 4) * 4u;
        int brow = wn * 32 + ((lane >> 4) << 3) + (lane & 7);
        uint32_t baddr = smem_u32(sH) + (uint32_t)(brow * 68 + ((lane >> 3) & 1) * 4) * 4u;

        float acc[4][4] = {};
        #pragma unroll
        for (int ks = 0; ks < 8; ks++) {
            int kb = ks * 8;
            uint32_t a0, a1, a2, a3;
            ldsm_x4(a0, a1, a2, a3, aaddr + kb * 4);
            #pragma unroll
            for (int p = 0; p < 2; p++) {
                uint32_t b0, b1, b2, b3;
                ldsm_x4(b0, b1, b2, b3, baddr + (p * 16 * 68 + kb) * 4);
                mma_tf32(acc[2 * p],     a0, a1, a2, a3, b0, b1);
                mma_tf32(acc[2 * p + 1], a0, a1, a2, a3, b2, b3);
            }
        }
        int m0 = wm * 16 + g, m1 = m0 + 8;
        float* Tt = g_buf1 + (size_t)BB * 1536;
        #pragma unroll
        for (int j = 0; j < 4; j++) {
            int r = wn * 32 + j * 8 + 2 * tg;
            size_t gr0 = row0 + r, gr1 = gr0 + 1;
            int b0i = (int)(gr0 / 96), n0i = (int)(gr0 % 96);
            int b1i = (int)(gr1 / 96), n1i = (int)(gr1 % 96);
            Tt[(size_t)b0i * 3072 + m0 * 96 + n0i] = tf32r(acc[j][0]);
            Tt[(size_t)b1i * 3072 + m0 * 96 + n1i] = tf32r(acc[j][1]);
            Tt[(size_t)b0i * 3072 + m1 * 96 + n0i] = tf32r(acc[j][2]);
            Tt[(size_t)b1i * 3072 + m1 * 96 + n1i] = tf32r(acc[j][3]);
        }
    }
}

// ---------------- gcnC via mma: out[b][pos][32ch] = relu(A@Tq + b2) ----------
__global__ void __launch_bounds__(256, 3) k_gcnCmma(const float* __restrict__ b2) {
    __shared__ float sA[128 * 36];
    __shared__ float sB[64 * 36];
    int t = threadIdx.x;
    int warp = t >> 5, lane = t & 31;
    int g = lane >> 2, tg = lane & 3;
    long n0 = (long)blockIdx.x * 64;
    int b0 = blockIdx.x * 2;
    const float* Tt = g_buf1 + (size_t)BB * 1536;   // [b][g][96n]
    float acc[8][4] = {};

    int atile = lane >> 3;
    int arow = warp * 16 + (lane & 7) + ((atile & 1) << 3);
    uint32_t aaddr = smem_u32(sA) + (uint32_t)(arow * 36 + (atile >> 1) * 4) * 4u;
    int brow = ((lane >> 4) << 3) + (lane & 7);
    uint32_t baddr = smem_u32(sB) + (uint32_t)(brow * 36 + ((lane >> 3) & 1) * 4) * 4u;

    for (int k0 = 0; k0 < 96; k0 += 32) {
        __syncthreads();
        for (int i = t; i < 128 * 8; i += 256) {
            int m = i >> 3, k4 = i & 7;
            *(float4*)&sA[m * 36 + k4 * 4] = *(const float4*)&g_Aq[m * 96 + k0 + k4 * 4];
        }
        for (int i = t; i < 64 * 8; i += 256) {   // float4: Tt contiguous in n(=k)
            int n = i >> 3, q = i & 7;
            int bi = n >> 5, gg = n & 31;
            *(float4*)&sB[n * 36 + q * 4] =
                *(const float4*)&Tt[(size_t)(b0 + bi) * 3072 + gg * 96 + k0 + q * 4];
        }
        __syncthreads();
        #pragma unroll
        for (int ks = 0; ks < 4; ks++) {
            int kb = ks * 8;
            uint32_t a0, a1, a2, a3;
            ldsm_x4(a0, a1, a2, a3, aaddr + kb * 4);
            #pragma unroll
            for (int p = 0; p < 4; p++) {
                uint32_t b0f, b1f, b2f, b3f;
                ldsm_x4(b0f, b1f, b2f, b3f, baddr + (p * 16 * 36 + kb) * 4);
                mma_tf32(acc[2 * p],     a0, a1, a2, a3, b0f, b1f);
                mma_tf32(acc[2 * p + 1], a0, a1, a2, a3, b2f, b3f);
            }
        }
    }
    int m0 = warp * 16 + g, m1 = m0 + 8;
    if (m0 < 96) {
        #pragma unroll
        for (int j = 0; j < 8; j++) {
            long nc = n0 + j * 8 + 2 * tg;
            int b = (int)(nc >> 5), gg = (int)(nc & 31);
            float bg0 = b2[gg], bg1 = b2[gg + 1];
            float* ob = g_buf2 + (size_t)b * 3072;        // [pos][32ch]
            ob[m0 * 32 + gg]     = tf32r(fmaxf(acc[j][0] + bg0, 0.f));
            ob[m0 * 32 + gg + 1] = tf32r(fmaxf(acc[j][1] + bg1, 0.f));
            ob[m1 * 32 + gg]     = tf32r(fmaxf(acc[j][2] + bg0, 0.f));
            ob[m1 * 32 + gg + 1] = tf32r(fmaxf(acc[j][3] + bg1, 0.f));
        }
    }
}

// ---------------- conv implicit GEMM, channel-last, cp.async 16B -------------
template<int M_BLK, int WM, int WN, int KTOT, int IC, int NPOS, int LIN, int PAD,
         int OC, int IO, size_t WOFF>
__global__ void __launch_bounds__(256, 3) k_convmma(const float* __restrict__ bias) {
    const float* w  = g_buf1 + WOFF;
    const float* in = (IO == 0) ? g_buf2 : g_buf1;
    float* outp     = (IO == 0) ? g_buf1 : g_buf2;
    constexpr int N_BLK = WN * 64;
    extern __shared__ float smd[];
    float* sA = smd;
    float* sB = smd + 2 * M_BLK * 36;
    int t = threadIdx.x;
    int warp = t >> 5, lane = t & 31;
    int g = lane >> 2, tg = lane & 3;
    int wm = warp % WM, wn = warp / WM;
    int mbase = blockIdx.y * M_BLK;
    long n0 = (long)blockIdx.x * N_BLK;

    float acc[8][4] = {};

    int atile = lane >> 3;
    int arow = wm * 16 + (lane & 7) + ((atile & 1) << 3);
    uint32_t aaddr = smem_u32(sA) + (uint32_t)(arow * 36 + (atile >> 1) * 4) * 4u;
    int brow = wn * 64 + ((lane >> 4) << 3) + (lane & 7);
    uint32_t baddr = smem_u32(sB) + (uint32_t)(brow * 36 + ((lane >> 3) & 1) * 4) * 4u;

    auto prefetch = [&](int k0, int s) {
        float* dA = sA + s * M_BLK * 36;
        for (int i = t; i < M_BLK * 8; i += 256) {
            int m = i >> 3, k4 = i & 7;
            cp_async16(smem_u32(&dA[m * 36 + k4 * 4]),
                       &w[(size_t)(mbase + m) * KTOT + k0 + k4 * 4]);
        }
        int kk = k0 / IC, ic0 = k0 % IC;
        float* dB = sB + s * N_BLK * 36;
        for (int i = t; i < N_BLK * 8; i += 256) {
            int n = i >> 3, q = i & 7;
            long ng = n0 + n;
            int b = (int)(ng / NPOS), p = (int)(ng % NPOS);
            int pos = p * 2 + kk - PAD;
            bool valid = (pos >= 0 && pos < LIN);
            const float* sp = &in[(size_t)b * 3072 + (valid ? pos : 0) * IC + ic0 + q * 4];
            cp_async16z(smem_u32(&dB[n * 36 + q * 4]), sp, valid);
        }
    };

    constexpr int NCH = KTOT / 32;
    prefetch(0, 0);
    cp_commit();
    for (int i = 0; i < NCH; i++) {
        int cur = i & 1;
        if (i + 1 < NCH) {
            prefetch((i + 1) * 32, cur ^ 1);
            cp_commit();
            cp_wait<1>();
        } else {
            cp_wait<0>();
        }
        __syncthreads();
        uint32_t aS = (uint32_t)cur * (M_BLK * 36 * 4);
        uint32_t bS = (uint32_t)cur * (N_BLK * 36 * 4);
        #pragma unroll
        for (int ks = 0; ks < 4; ks++) {
            int kb = ks * 8;
            uint32_t a0, a1, a2, a3;
            ldsm_x4(a0, a1, a2, a3, aaddr + aS + kb * 4);
            #pragma unroll
            for (int p = 0; p < 4; p++) {
                uint32_t b0, b1, b2, b3;
                ldsm_x4(b0, b1, b2, b3, baddr + bS + (p * 16 * 36 + kb) * 4);
                mma_tf32(acc[2 * p],     a0, a1, a2, a3, b0, b1);
                mma_tf32(acc[2 * p + 1], a0, a1, a2, a3, b2, b3);
            }
        }
        __syncthreads();
    }
    int m0 = mbase + wm * 16 + g;
    int m1 = m0 + 8;
    float bi0 = bias[m0], bi1 = bias[m1];
    #pragma unroll
    for (int j = 0; j < 8; j++) {
        long nc = n0 + wn * 64 + j * 8 + 2 * tg;
        int b = (int)(nc / NPOS), p = (int)(nc % NPOS);
        float* ob = outp + (size_t)b * 3072;
        ob[p * OC + m0]       = tf32r(fmaxf(acc[j][0] + bi0, 0.f));
        ob[(p + 1) * OC + m0] = tf32r(fmaxf(acc[j][1] + bi0, 0.f));
        ob[p * OC + m1]       = tf32r(fmaxf(acc[j][2] + bi1, 0.f));
        ob[(p + 1) * OC + m1] = tf32r(fmaxf(acc[j][3] + bi1, 0.f));
    }
}

// ---------------- fc1 via mma, cp.async, N_BLK=64 ----------------------------
__global__ void __launch_bounds__(256, 3) k_fc1mma(const float* __restrict__ bias,
                                                   float* __restrict__ feat_out) {
    const float* Wt = g_buf1 + WT_OFF;
    extern __shared__ float smd[];
    float* sA = smd;                   // [2][128*36]
    float* sB = smd + 2 * 128 * 36;    // [2][64*36]
    int t = threadIdx.x;
    int warp = t >> 5, lane = t & 31;
    int g = lane >> 2, tg = lane & 3;
    long n0 = (long)blockIdx.x * 64;
    float acc[8][4] = {};

    int atile = lane >> 3;
    int arow = warp * 16 + (lane & 7) + ((atile & 1) << 3);
    uint32_t aaddr = smem_u32(sA) + (uint32_t)(arow * 36 + (atile >> 1) * 4) * 4u;
    int brow = ((lane >> 4) << 3) + (lane & 7);
    uint32_t baddr = smem_u32(sB) + (uint32_t)(brow * 36 + ((lane >> 3) & 1) * 4) * 4u;

    auto prefetch = [&](int k0, int s) {
        float* dA = sA + s * 128 * 36;
        for (int i = t; i < 1024; i += 256) {
            int m = i >> 3, k4 = i & 7;
            cp_async16(smem_u32(&dA[m * 36 + k4 * 4]),
                       &Wt[(size_t)m * 3072 + k0 + k4 * 4]);
        }
        float* dB = sB + s * 64 * 36;
        for (int i = t; i < 512; i += 256) {
            int n = i >> 3, k4 = i & 7;
            cp_async16(smem_u32(&dB[n * 36 + k4 * 4]),
                       &g_buf1[(size_t)(n0 + n) * 3072 + k0 + k4 * 4]);
        }
    };

    prefetch(0, 0);
    cp_commit();
    for (int i = 0; i < 96; i++) {
        int cur = i & 1;
        if (i + 1 < 96) {
            prefetch((i + 1) * 32, cur ^ 1);
            cp_commit();
            cp_wait<1>();
        } else {
            cp_wait<0>();
        }
        __syncthreads();
        uint32_t aS = (uint32_t)cur * (128 * 36 * 4);
        uint32_t bS = (uint32_t)cur * (64 * 36 * 4);
        #pragma unroll
        for (int ks = 0; ks < 4; ks++) {
            int kb = ks * 8;
            uint32_t a0, a1, a2, a3;
            ldsm_x4(a0, a1, a2, a3, aaddr + aS + kb * 4);
            #pragma unroll
            for (int p = 0; p < 4; p++) {
                uint32_t b0, b1, b2, b3;
                ldsm_x4(b0, b1, b2, b3, baddr + bS + (p * 16 * 36 + kb) * 4);
                mma_tf32(acc[2 * p],     a0, a1, a2, a3, b0, b1);
                mma_tf32(acc[2 * p + 1], a0, a1, a2, a3, b2, b3);
            }
        }
        __syncthreads();
    }
    int m0 = warp * 16 + g, m1 = m0 + 8;
    float bi0 = bias[m0], bi1 = bias[m1];
    #pragma unroll
    for (int j = 0; j < 8; j++) {
        long n = n0 + j * 8 + 2 * tg;
        float f00 = acc[j][0] + bi0, f01 = acc[j][1] + bi0;
        float f10 = acc[j][2] + bi1, f11 = acc[j][3] + bi1;
        feat_out[n * 128 + m0] = f00;       feat_out[(n + 1) * 128 + m0] = f01;
        feat_out[n * 128 + m1] = f10;       feat_out[(n + 1) * 128 + m1] = f11;
        g_buf2[n * 128 + m0] = tf32r(fmaxf(f00, 0.f));
        g_buf2[(n + 1) * 128 + m0] = tf32r(fmaxf(f01, 0.f));
        g_buf2[n * 128 + m1] = tf32r(fmaxf(f10, 0.f));
        g_buf2[(n + 1) * 128 + m1] = tf32r(fmaxf(f11, 0.f));
    }
}

// ---------------- cls via mma: pre-rounded transposed weights ----------------
template<int MTOT, int STAGE, size_t CWOFF>
__global__ void __launch_bounds__(256, 3) k_clsmma(const float* __restrict__ bias,
                                                   float* __restrict__ outx) {
    const float* inb = (STAGE == 1) ? g_buf2 : g_buf1;
    const float* Wm  = g_buf1 + CWOFF;
    __shared__ float sA[128 * 36];
    __shared__ float sB[64 * 36];
    int t = threadIdx.x;
    int warp = t >> 5, lane = t & 31;
    int g = lane >> 2, tg = lane & 3;
    int mbase = blockIdx.y * 128;
    long n0 = (long)blockIdx.x * 64;
    float acc[8][4] = {};

    int atile = lane >> 3;
    int arow = warp * 16 + (lane & 7) + ((atile & 1) << 3);
    uint32_t aaddr = smem_u32(sA) + (uint32_t)(arow * 36 + (atile >> 1) * 4) * 4u;
    int brow = ((lane >> 4) << 3) + (lane & 7);
    uint32_t baddr = smem_u32(sB) + (uint32_t)(brow * 36 + ((lane >> 3) & 1) * 4) * 4u;

    for (int k0 = 0; k0 < 128; k0 += 32) {
        __syncthreads();
        for (int i = t; i < 128 * 8; i += 256) {
            int n = i >> 3, k4 = i & 7;
            *(float4*)&sA[n * 36 + k4 * 4] =
                *(const float4*)&Wm[(size_t)(mbase + n) * 128 + k0 + k4 * 4];
        }
        for (int i = t; i < 512; i += 256) {
            int n = i >> 3, k4 = i & 7;
            float4 v = *(const float4*)&inb[(size_t)(n0 + n) * 128 + k0 + k4 * 4];
            *(float4*)&sB[n * 36 + k4 * 4] = v;
        }
        __syncthreads();
        #pragma unroll
        for (int ks = 0; ks < 4; ks++) {
            int kb = ks * 8;
            uint32_t a0, a1, a2, a3;
            ldsm_x4(a0, a1, a2, a3, aaddr + kb * 4);
            #pragma unroll
            for (int p = 0; p < 4; p++) {
                uint32_t b0, b1, b2, b3;
                ldsm_x4(b0, b1, b2, b3, baddr + (p * 16 * 36 + kb) * 4);
                mma_tf32(acc[2 * p],     a0, a1, a2, a3, b0, b1);
                mma_tf32(acc[2 * p + 1], a0, a1, a2, a3, b2, b3);
            }
        }
    }
    int m0 = mbase + warp * 16 + g, m1 = m0 + 8;
    float bi0 = (m0 < MTOT) ? bias[m0] : 0.f;
    float bi1 = (m1 < MTOT) ? bias[m1] : 0.f;
    #pragma unroll
    for (int j = 0; j < 8; j++) {
        long b = n0 + j * 8 + 2 * tg;
        float f00 = acc[j][0] + bi0, f01 = acc[j][1] + bi0;
        float f10 = acc[j][2] + bi1, f11 = acc[j][3] + bi1;
        if (STAGE == 1) {
            f00 = tf32r(fmaxf(f00, 0.f)); f01 = tf32r(fmaxf(f01, 0.f));
            f10 = tf32r(fmaxf(f10, 0.f)); f11 = tf32r(fmaxf(f11, 0.f));
            g_buf1[b * 128 + m0] = f00; g_buf1[(b + 1) * 128 + m0] = f01;
            g_buf1[b * 128 + m1] = f10; g_buf1[(b + 1) * 128 + m1] = f11;
        } else {
            if (m0 < MTOT) { outx[b * MTOT + m0] = f00; outx[(b + 1) * MTOT + m0] = f01; }
            if (m1 < MTOT) { outx[b * MTOT + m1] = f10; outx[(b + 1) * MTOT + m1] = f11; }
        }
    }
}

// ---------------- launch ------------------------------------------------------
extern "C" void kernel_launch(void* const* d_in, const int* in_sizes, int n_in,
                              void* d_out, int out_size) {
    const float* src     = (const float*)d_in[0];
    const int*   ei      = (const int*)d_in[1];
    const float* gcn1_w  = (const float*)d_in[2];
    const float* gcn1_b  = (const float*)d_in[3];
    const float* gcn2_w  = (const float*)d_in[4];
    const float* gcn2_b  = (const float*)d_in[5];
    const float* conv1_w = (const float*)d_in[6];
    const float* conv1_b = (const float*)d_in[7];
    const float* conv2_w = (const float*)d_in[8];
    const float* conv2_b = (const float*)d_in[9];
    const float* conv3_w = (const float*)d_in[10];
    const float* conv3_b = (const float*)d_in[11];
    const float* fc1_w   = (const float*)d_in[12];
    const float* fc1_b   = (const float*)d_in[13];
    const float* cls1_w  = (const float*)d_in[14];
    const float* cls1_b  = (const float*)d_in[15];
    const float* cls2_w  = (const float*)d_in[16];
    const float* cls2_b  = (const float*)d_in[17];

    int ne = in_sizes[1] / 2;

    float* out   = (float*)d_out;
    float* out_x = out;                          // [B,210]
    float* out_f = out + (size_t)BB * 210;       // [B,128]

    const int GCNB_SMEM = (64 * 20 + 32 * 68 + 128 * 20 + 128 * 68 + 64) * 4;
    const int CONV_SMEM = 2 * 192 * 36 * 4;      // 55296
    const int FC1_SMEM  = 2 * 192 * 36 * 4;      // 55296

    cudaFuncSetAttribute(k_gcnBmma, cudaFuncAttributeMaxDynamicSharedMemorySize, GCNB_SMEM);
    cudaFuncSetAttribute(k_convmma<64, 4, 2, 224, 32, 48, 96, 3, 64, 0, CW1_OFF>,
                         cudaFuncAttributeMaxDynamicSharedMemorySize, CONV_SMEM);
    cudaFuncSetAttribute(k_convmma<128, 8, 1, 320, 64, 24, 48, 2, 128, 1, CW2_OFF>,
                         cudaFuncAttributeMaxDynamicSharedMemorySize, CONV_SMEM);
    cudaFuncSetAttribute(k_convmma<128, 8, 1, 384, 128, 12, 24, 1, 256, 0, CW3_OFF>,
                         cudaFuncAttributeMaxDynamicSharedMemorySize, CONV_SMEM);
    cudaFuncSetAttribute(k_fc1mma, cudaFuncAttributeMaxDynamicSharedMemorySize, FC1_SMEM);

    k_build_adj<<<1, 256>>>(ei, ne);
    k_prea<<<48, 256>>>();
    k_trW<<<1536, 256>>>(fc1_w);
    k_prew<<<384, 256>>>(conv1_w, conv2_w, conv3_w, cls1_w, cls2_w);

    k_gcnAmma<<<2048, 256>>>(src);
    k_gcnBmma<<<BB * 96 / 128, 256, GCNB_SMEM>>>(gcn1_w, gcn1_b, gcn2_w);
    k_gcnCmma<<<4096, 256>>>(gcn2_b);

    k_convmma<64, 4, 2, 224, 32, 48, 96, 3, 64, 0, CW1_OFF>
        <<<dim3(3072, 1), 256, CONV_SMEM>>>(conv1_b);
    k_convmma<128, 8, 1, 320, 64, 24, 48, 2, 128, 1, CW2_OFF>
        <<<dim3(3072, 1), 256, CONV_SMEM>>>(conv2_b);
    k_convmma<128, 8, 1, 384, 128, 12, 24, 1, 256, 0, CW3_OFF>
        <<<dim3(1536, 2), 256, CONV_SMEM>>>(conv3_b);

    k_fc1mma<<<128, 256, FC1_SMEM>>>(fc1_b, out_f);
    k_clsmma<128, 1, CWC1_OFF><<<dim3(128, 1), 256>>>(cls1_b, nullptr);
    k_clsmma<210, 2, CWC2_OFF><<<dim3(128, 2), 256>>>(cls2_b, out_x);
}

// round 16
// speedup vs baseline: 1.0094x; 1.0094x over previous
#include <cuda_runtime.h>
#include <cstdint>
#include <math.h>

#define BB 8192

__device__ __forceinline__ float tf32r(float x) {
    uint32_t u;
    asm("cvt.rna.tf32.f32 %0, %1;" : "=r"(u) : "f"(x));
    return __uint_as_float(u);
}

__device__ __forceinline__ void mma_tf32(float c[4],
                                         uint32_t a0, uint32_t a1, uint32_t a2, uint32_t a3,
                                         uint32_t b0, uint32_t b1) {
    asm volatile(
        "mma.sync.aligned.m16n8k8.row.col.f32.tf32.tf32.f32 "
        "{%0,%1,%2,%3}, {%4,%5,%6,%7}, {%8,%9}, {%0,%1,%2,%3};"
        : "+f"(c[0]), "+f"(c[1]), "+f"(c[2]), "+f"(c[3])
        : "r"(a0), "r"(a1), "r"(a2), "r"(a3), "r"(b0), "r"(b1));
}

__device__ __forceinline__ void ldsm_x4(uint32_t& r0, uint32_t& r1, uint32_t& r2, uint32_t& r3,
                                        uint32_t addr) {
    asm volatile("ldmatrix.sync.aligned.m8n8.x4.shared.b16 {%0,%1,%2,%3}, [%4];"
                 : "=r"(r0), "=r"(r1), "=r"(r2), "=r"(r3) : "r"(addr));
}

__device__ __forceinline__ uint32_t smem_u32(const void* p) {
    return (uint32_t)__cvta_generic_to_shared(p);
}

__device__ __forceinline__ void cp_async16(uint32_t dst, const void* src) {
    asm volatile("cp.async.cg.shared.global [%0], [%1], 16;" :: "r"(dst), "l"(src));
}
__device__ __forceinline__ void cp_async16z(uint32_t dst, const void* src, bool valid) {
    int sz = valid ? 16 : 0;
    asm volatile("cp.async.cg.shared.global [%0], [%1], 16, %2;"
                 :: "r"(dst), "l"(src), "r"(sz));
}
__device__ __forceinline__ void cp_commit() {
    asm volatile("cp.async.commit_group;");
}
template<int N>
__device__ __forceinline__ void cp_wait() {
    asm volatile("cp.async.wait_group %0;" :: "n"(N));
}

// ---------------- scratch ----------------------------------------------------
// g_buf1: Y/conv [0,B*3072) | FACC [B*3072,B*3072+2*B*128) | Tt [B*1536,B*4608)*
//   (*Tt overlaps conv region but is dead before conv1 writes; FACC region is
//    dead Tt space, used only during fc1 which reads [0,B*3072) exclusively.)
// Then: Wt | CW1 | CW2 | CW3 | CWC1 | CWC2
__device__ float g_A[96 * 96];
__device__ float g_Aq[128 * 96];
__device__ float g_buf1[(size_t)BB * 6144];
__device__ float g_buf2[(size_t)BB * 3072];

constexpr size_t FACC_OFF = (size_t)BB * 3072;
constexpr size_t WT_OFF   = (size_t)BB * 4608;
constexpr size_t CW1_OFF  = WT_OFF + 393216;
constexpr size_t CW2_OFF  = CW1_OFF + 14336;
constexpr size_t CW3_OFF  = CW2_OFF + 40960;
constexpr size_t CWC1_OFF = CW3_OFF + 98304;
constexpr size_t CWC2_OFF = CWC1_OFF + 16384;

// ---------------- adjacency: build + round + pad (single block) --------------
__global__ void k_build_adj(const int* __restrict__ ei, int ne) {
    __shared__ float deg[96];
    __shared__ float dinv[96];
    int t = threadIdx.x;
    if (t < 96) deg[t] = 0.f;
    for (int i = t; i < 9216; i += 256) g_A[i] = 0.f;
    __syncthreads();
    for (int e = t; e < ne; e += 256) atomicAdd(&deg[ei[e]], 1.0f);
    if (t < 96) atomicAdd(&deg[t], 1.0f);
    __syncthreads();
    if (t < 96) dinv[t] = 1.0f / sqrtf(fmaxf(deg[t], 1e-12f));
    __syncthreads();
    for (int e = t; e < ne; e += 256) {
        int r = ei[e], c = ei[ne + e];
        atomicAdd(&g_A[r * 96 + c], dinv[r] * dinv[c]);
    }
    if (t < 96) atomicAdd(&g_A[t * 96 + t], dinv[t] * dinv[t]);
    __syncthreads();
    for (int i = t; i < 128 * 96; i += 256)
        g_Aq[i] = (i < 9216) ? tf32r(g_A[i]) : 0.f;
}

// ---------------- merged weight prep (trW + conv reorder + cls transpose) ----
__global__ void k_prep(const float* __restrict__ W, const float* __restrict__ w1,
                       const float* __restrict__ w2, const float* __restrict__ w3,
                       const float* __restrict__ c1, const float* __restrict__ c2) {
    int i = blockIdx.x * 256 + threadIdx.x;
    if (i < 393216) {                              // fc1: Wt[m][p*256+c]
        int m = i / 3072, kn = i % 3072;
        int p = kn >> 8, c = kn & 255;
        g_buf1[WT_OFF + i] = tf32r(W[(size_t)(c * 12 + p) * 128 + m]);
    }
    if (i < 14336) {
        int o = i / 224, r = i % 224, ic = r / 7, kk = r % 7;
        g_buf1[CW1_OFF + o * 224 + kk * 32 + ic] = tf32r(w1[i]);
    }
    if (i < 40960) {
        int o = i / 320, r = i % 320, ic = r / 5, kk = r % 5;
        g_buf1[CW2_OFF + o * 320 + kk * 64 + ic] = tf32r(w2[i]);
    }
    if (i < 98304) {
        int o = i / 384, r = i % 384, ic = r / 3, kk = r % 3;
        g_buf1[CW3_OFF + o * 384 + kk * 128 + ic] = tf32r(w3[i]);
    }
    if (i < 16384) {
        int m = i >> 7, k = i & 127;
        g_buf1[CWC1_OFF + i] = tf32r(c1[(size_t)k * 128 + m]);
    }
    if (i < 32768) {
        int m = i >> 7, k = i & 127;
        g_buf1[CWC2_OFF + i] = (m < 210) ? tf32r(c2[(size_t)k * 210 + m]) : 0.f;
    }
}

// ---------------- gcnA via mma: Y[n,(b,c)] = A@Xq ----------------------------
__global__ void __launch_bounds__(256, 3) k_gcnAmma(const float* __restrict__ src) {
    __shared__ float sA[128 * 36];
    __shared__ float sB[64 * 36];
    int t = threadIdx.x;
    int warp = t >> 5, lane = t & 31;
    int g = lane >> 2, tg = lane & 3;
    long n0 = (long)blockIdx.x * 64;
    float acc[8][4] = {};

    int atile = lane >> 3;
    int arow = warp * 16 + (lane & 7) + ((atile & 1) << 3);
    uint32_t aaddr = smem_u32(sA) + (uint32_t)(arow * 36 + (atile >> 1) * 4) * 4u;
    int brow = ((lane >> 4) << 3) + (lane & 7);
    uint32_t baddr = smem_u32(sB) + (uint32_t)(brow * 36 + ((lane >> 3) & 1) * 4) * 4u;

    for (int k0 = 0; k0 < 96; k0 += 32) {
        __syncthreads();
        for (int i = t; i < 128 * 8; i += 256) {
            int m = i >> 3, k4 = i & 7;
            *(float4*)&sA[m * 36 + k4 * 4] = *(const float4*)&g_Aq[m * 96 + k0 + k4 * 4];
        }
        for (int i = t; i < 64 * 8; i += 256) {
            int n = i >> 3, q = i & 7;
            long col = n0 + n;
            int b = (int)(col >> 4), c = (int)(col & 15);
            float4 v = *(const float4*)&src[(size_t)b * 1536 + c * 96 + k0 + q * 4];
            v.x = tf32r(v.x); v.y = tf32r(v.y); v.z = tf32r(v.z); v.w = tf32r(v.w);
            *(float4*)&sB[n * 36 + q * 4] = v;
        }
        __syncthreads();
        #pragma unroll
        for (int ks = 0; ks < 4; ks++) {
            int kb = ks * 8;
            uint32_t a0, a1, a2, a3;
            ldsm_x4(a0, a1, a2, a3, aaddr + kb * 4);
            #pragma unroll
            for (int p = 0; p < 4; p++) {
                uint32_t b0, b1, b2, b3;
                ldsm_x4(b0, b1, b2, b3, baddr + (p * 16 * 36 + kb) * 4);
                mma_tf32(acc[2 * p],     a0, a1, a2, a3, b0, b1);
                mma_tf32(acc[2 * p + 1], a0, a1, a2, a3, b2, b3);
            }
        }
    }
    int m0 = warp * 16 + g, m1 = m0 + 8;
    if (m0 < 96) {
        #pragma unroll
        for (int j = 0; j < 8; j++) {
            long nc = n0 + j * 8 + 2 * tg;
            int b = (int)(nc >> 4), c = (int)(nc & 15);
            float* yb = g_buf1 + (size_t)b * 1536;
            yb[m0 * 16 + c]     = acc[j][0];
            yb[m0 * 16 + c + 1] = acc[j][1];
            yb[m1 * 16 + c]     = acc[j][2];
            yb[m1 * 16 + c + 1] = acc[j][3];
        }
    }
}

// ---------------- gcnB via fused 2-stage mma (Tt stored transposed+rounded) --
__global__ void __launch_bounds__(256, 3) k_gcnBmma(const float* __restrict__ W1,
                                                    const float* __restrict__ b1,
                                                    const float* __restrict__ W2) {
    extern __shared__ float sm[];
    float* sW1 = sm;
    float* sW2 = sW1 + 64 * 20;
    float* sY  = sW2 + 32 * 68;
    float* sH  = sY + 128 * 20;
    float* sB1 = sH + 128 * 68;
    int t = threadIdx.x;
    int warp = t >> 5, lane = t & 31;
    int g = lane >> 2, tg = lane & 3;
    size_t row0 = (size_t)blockIdx.x * 128;

    for (int i = t; i < 1024; i += 256) {
        int c = i >> 6, f = i & 63;
        sW1[f * 20 + c] = tf32r(W1[i]);
    }
    for (int i = t; i < 2048; i += 256) {
        int f = i >> 5, gg = i & 31;
        sW2[gg * 68 + f] = tf32r(W2[i]);
    }
    if (t < 64) sB1[t] = b1[t];
    for (int i = t; i < 128 * 4; i += 256) {
        int r = i >> 2, c4 = i & 3;
        float4 v = *(const float4*)&g_buf1[(row0 + r) * 16 + c4 * 4];
        v.x = tf32r(v.x); v.y = tf32r(v.y); v.z = tf32r(v.z); v.w = tf32r(v.w);
        *(float4*)&sY[r * 20 + c4 * 4] = v;
    }
    __syncthreads();

    {   // stage 1
        int wm = warp & 3, wn = warp >> 2;
        int atile = lane >> 3;
        int arow = wm * 16 + (lane & 7) + ((atile & 1) << 3);
        uint32_t aaddr = smem_u32(sW1) + (uint32_t)(arow * 20 + (atile >> 1) * 4) * 4u;
        int brow = wn * 64 + ((lane >> 4) << 3) + (lane & 7);
        uint32_t baddr = smem_u32(sY) + (uint32_t)(brow * 20 + ((lane >> 3) & 1) * 4) * 4u;

        float acc[8][4] = {};
        #pragma unroll
        for (int ks = 0; ks < 2; ks++) {
            int kb = ks * 8;
            uint32_t a0, a1, a2, a3;
            ldsm_x4(a0, a1, a2, a3, aaddr + kb * 4);
            #pragma unroll
            for (int p = 0; p < 4; p++) {
                uint32_t b0, b1, b2, b3;
                ldsm_x4(b0, b1, b2, b3, baddr + (p * 16 * 20 + kb) * 4);
                mma_tf32(acc[2 * p],     a0, a1, a2, a3, b0, b1);
                mma_tf32(acc[2 * p + 1], a0, a1, a2, a3, b2, b3);
            }
        }
        int m0 = wm * 16 + g, m1 = m0 + 8;
        float bi0 = sB1[m0], bi1 = sB1[m1];
        #pragma unroll
        for (int j = 0; j < 8; j++) {
            int r = wn * 64 + j * 8 + 2 * tg;
            sH[r * 68 + m0]       = tf32r(fmaxf(acc[j][0] + bi0, 0.f));
            sH[(r + 1) * 68 + m0] = tf32r(fmaxf(acc[j][1] + bi0, 0.f));
            sH[r * 68 + m1]       = tf32r(fmaxf(acc[j][2] + bi1, 0.f));
            sH[(r + 1) * 68 + m1] = tf32r(fmaxf(acc[j][3] + bi1, 0.f));
        }
    }
    __syncthreads();

    {   // stage 2: Tt[b][g][96n]
        int wm = warp & 1, wn = warp >> 1;
        int atile = lane >> 3;
        int arow = wm * 16 + (lane & 7) + ((atile & 1) << 3);
        uint32_t aaddr = smem_u32(sW2) + (uint32_t)(arow * 68 + (atile >> 1) * 4) * 4u;
        int brow = wn * 32 + ((lane >> 4) << 3) + (lane & 7);
        uint32_t baddr = smem_u32(sH) + (uint32_t)(brow * 68 + ((lane >> 3) & 1) * 4) * 4u;

        float acc[4][4] = {};
        #pragma unroll
        for (int ks = 0; ks < 8; ks++) {
            int kb = ks * 8;
            uint32_t a0, a1, a2, a3;
            ldsm_x4(a0, a1, a2, a3, aaddr + kb * 4);
            #pragma unroll
            for (int p = 0; p < 2; p++) {
                uint32_t b0, b1, b2, b3;
                ldsm_x4(b0, b1, b2, b3, baddr + (p * 16 * 68 + kb) * 4);
                mma_tf32(acc[2 * p],     a0, a1, a2, a3, b0, b1);
                mma_tf32(acc[2 * p + 1], a0, a1, a2, a3, b2, b3);
            }
        }
        int m0 = wm * 16 + g, m1 = m0 + 8;
        float* Tt = g_buf1 + (size_t)BB * 1536;
        #pragma unroll
        for (int j = 0; j < 4; j++) {
            int r = wn * 32 + j * 8 + 2 * tg;
            size_t gr0 = row0 + r, gr1 = gr0 + 1;
            int b0i = (int)(gr0 / 96), n0i = (int)(gr0 % 96);
            int b1i = (int)(gr1 / 96), n1i = (int)(gr1 % 96);
            Tt[(size_t)b0i * 3072 + m0 * 96 + n0i] = tf32r(acc[j][0]);
            Tt[(size_t)b1i * 3072 + m0 * 96 + n1i] = tf32r(acc[j][1]);
            Tt[(size_t)b0i * 3072 + m1 * 96 + n0i] = tf32r(acc[j][2]);
            Tt[(size_t)b1i * 3072 + m1 * 96 + n1i] = tf32r(acc[j][3]);
        }
    }
}

// ---------------- gcnC via mma: out[b][pos][32ch] = relu(A@Tq + b2) ----------
__global__ void __launch_bounds__(256, 3) k_gcnCmma(const float* __restrict__ b2) {
    __shared__ float sA[128 * 36];
    __shared__ float sB[64 * 36];
    int t = threadIdx.x;
    int warp = t >> 5, lane = t & 31;
    int g = lane >> 2, tg = lane & 3;
    long n0 = (long)blockIdx.x * 64;
    int b0 = blockIdx.x * 2;
    const float* Tt = g_buf1 + (size_t)BB * 1536;
    float acc[8][4] = {};

    int atile = lane >> 3;
    int arow = warp * 16 + (lane & 7) + ((atile & 1) << 3);
    uint32_t aaddr = smem_u32(sA) + (uint32_t)(arow * 36 + (atile >> 1) * 4) * 4u;
    int brow = ((lane >> 4) << 3) + (lane & 7);
    uint32_t baddr = smem_u32(sB) + (uint32_t)(brow * 36 + ((lane >> 3) & 1) * 4) * 4u;

    for (int k0 = 0; k0 < 96; k0 += 32) {
        __syncthreads();
        for (int i = t; i < 128 * 8; i += 256) {
            int m = i >> 3, k4 = i & 7;
            *(float4*)&sA[m * 36 + k4 * 4] = *(const float4*)&g_Aq[m * 96 + k0 + k4 * 4];
        }
        for (int i = t; i < 64 * 8; i += 256) {
            int n = i >> 3, q = i & 7;
            int bi = n >> 5, gg = n & 31;
            *(float4*)&sB[n * 36 + q * 4] =
                *(const float4*)&Tt[(size_t)(b0 + bi) * 3072 + gg * 96 + k0 + q * 4];
        }
        __syncthreads();
        #pragma unroll
        for (int ks = 0; ks < 4; ks++) {
            int kb = ks * 8;
            uint32_t a0, a1, a2, a3;
            ldsm_x4(a0, a1, a2, a3, aaddr + kb * 4);
            #pragma unroll
            for (int p = 0; p < 4; p++) {
                uint32_t b0f, b1f, b2f, b3f;
                ldsm_x4(b0f, b1f, b2f, b3f, baddr + (p * 16 * 36 + kb) * 4);
                mma_tf32(acc[2 * p],     a0, a1, a2, a3, b0f, b1f);
                mma_tf32(acc[2 * p + 1], a0, a1, a2, a3, b2f, b3f);
            }
        }
    }
    int m0 = warp * 16 + g, m1 = m0 + 8;
    if (m0 < 96) {
        #pragma unroll
        for (int j = 0; j < 8; j++) {
            long nc = n0 + j * 8 + 2 * tg;
            int b = (int)(nc >> 5), gg = (int)(nc & 31);
            float bg0 = b2[gg], bg1 = b2[gg + 1];
            float* ob = g_buf2 + (size_t)b * 3072;
            ob[m0 * 32 + gg]     = tf32r(fmaxf(acc[j][0] + bg0, 0.f));
            ob[m0 * 32 + gg + 1] = tf32r(fmaxf(acc[j][1] + bg1, 0.f));
            ob[m1 * 32 + gg]     = tf32r(fmaxf(acc[j][2] + bg0, 0.f));
            ob[m1 * 32 + gg + 1] = tf32r(fmaxf(acc[j][3] + bg1, 0.f));
        }
    }
}

// ---------------- conv implicit GEMM, channel-last, cp.async 16B -------------
template<int M_BLK, int WM, int WN, int KTOT, int IC, int NPOS, int LIN, int PAD,
         int OC, int IO, size_t WOFF>
__global__ void __launch_bounds__(256, 3) k_convmma(const float* __restrict__ bias) {
    const float* w  = g_buf1 + WOFF;
    const float* in = (IO == 0) ? g_buf2 : g_buf1;
    float* outp     = (IO == 0) ? g_buf1 : g_buf2;
    constexpr int N_BLK = WN * 64;
    extern __shared__ float smd[];
    float* sA = smd;
    float* sB = smd + 2 * M_BLK * 36;
    int t = threadIdx.x;
    int warp = t >> 5, lane = t & 31;
    int g = lane >> 2, tg = lane & 3;
    int wm = warp % WM, wn = warp / WM;
    int mbase = blockIdx.y * M_BLK;
    long n0 = (long)blockIdx.x * N_BLK;

    float acc[8][4] = {};

    int atile = lane >> 3;
    int arow = wm * 16 + (lane & 7) + ((atile & 1) << 3);
    uint32_t aaddr = smem_u32(sA) + (uint32_t)(arow * 36 + (atile >> 1) * 4) * 4u;
    int brow = wn * 64 + ((lane >> 4) << 3) + (lane & 7);
    uint32_t baddr = smem_u32(sB) + (uint32_t)(brow * 36 + ((lane >> 3) & 1) * 4) * 4u;

    auto prefetch = [&](int k0, int s) {
        float* dA = sA + s * M_BLK * 36;
        for (int i = t; i < M_BLK * 8; i += 256) {
            int m = i >> 3, k4 = i & 7;
            cp_async16(smem_u32(&dA[m * 36 + k4 * 4]),
                       &w[(size_t)(mbase + m) * KTOT + k0 + k4 * 4]);
        }
        int kk = k0 / IC, ic0 = k0 % IC;
        float* dB = sB + s * N_BLK * 36;
        for (int i = t; i < N_BLK * 8; i += 256) {
            int n = i >> 3, q = i & 7;
            long ng = n0 + n;
            int b = (int)(ng / NPOS), p = (int)(ng % NPOS);
            int pos = p * 2 + kk - PAD;
            bool valid = (pos >= 0 && pos < LIN);
            const float* sp = &in[(size_t)b * 3072 + (valid ? pos : 0) * IC + ic0 + q * 4];
            cp_async16z(smem_u32(&dB[n * 36 + q * 4]), sp, valid);
        }
    };

    constexpr int NCH = KTOT / 32;
    prefetch(0, 0);
    cp_commit();
    for (int i = 0; i < NCH; i++) {
        int cur = i & 1;
        if (i + 1 < NCH) {
            prefetch((i + 1) * 32, cur ^ 1);
            cp_commit();
            cp_wait<1>();
        } else {
            cp_wait<0>();
        }
        __syncthreads();
        uint32_t aS = (uint32_t)cur * (M_BLK * 36 * 4);
        uint32_t bS = (uint32_t)cur * (N_BLK * 36 * 4);
        #pragma unroll
        for (int ks = 0; ks < 4; ks++) {
            int kb = ks * 8;
            uint32_t a0, a1, a2, a3;
            ldsm_x4(a0, a1, a2, a3, aaddr + aS + kb * 4);
            #pragma unroll
            for (int p = 0; p < 4; p++) {
                uint32_t b0, b1, b2, b3;
                ldsm_x4(b0, b1, b2, b3, baddr + bS + (p * 16 * 36 + kb) * 4);
                mma_tf32(acc[2 * p],     a0, a1, a2, a3, b0, b1);
                mma_tf32(acc[2 * p + 1], a0, a1, a2, a3, b2, b3);
            }
        }
        __syncthreads();
    }
    int m0 = mbase + wm * 16 + g;
    int m1 = m0 + 8;
    float bi0 = bias[m0], bi1 = bias[m1];
    #pragma unroll
    for (int j = 0; j < 8; j++) {
        long nc = n0 + wn * 64 + j * 8 + 2 * tg;
        int b = (int)(nc / NPOS), p = (int)(nc % NPOS);
        float* ob = outp + (size_t)b * 3072;
        ob[p * OC + m0]       = tf32r(fmaxf(acc[j][0] + bi0, 0.f));
        ob[(p + 1) * OC + m0] = tf32r(fmaxf(acc[j][1] + bi0, 0.f));
        ob[p * OC + m1]       = tf32r(fmaxf(acc[j][2] + bi1, 0.f));
        ob[(p + 1) * OC + m1] = tf32r(fmaxf(acc[j][3] + bi1, 0.f));
    }
}

// ---------------- fc1 via mma, split-K x2, partials to FACC ------------------
__global__ void __launch_bounds__(256, 3) k_fc1mma() {
    const float* Wt = g_buf1 + WT_OFF;
    extern __shared__ float smd[];
    float* sA = smd;                   // [2][128*36]
    float* sB = smd + 2 * 128 * 36;    // [2][64*36]
    int t = threadIdx.x;
    int warp = t >> 5, lane = t & 31;
    int g = lane >> 2, tg = lane & 3;
    long n0 = (long)blockIdx.x * 64;
    int kh = blockIdx.y;               // k-half: 0 or 1
    int kbase = kh * 1536;
    float acc[8][4] = {};

    int atile = lane >> 3;
    int arow = warp * 16 + (lane & 7) + ((atile & 1) << 3);
    uint32_t aaddr = smem_u32(sA) + (uint32_t)(arow * 36 + (atile >> 1) * 4) * 4u;
    int brow = ((lane >> 4) << 3) + (lane & 7);
    uint32_t baddr = smem_u32(sB) + (uint32_t)(brow * 36 + ((lane >> 3) & 1) * 4) * 4u;

    auto prefetch = [&](int k0, int s) {
        float* dA = sA + s * 128 * 36;
        for (int i = t; i < 1024; i += 256) {
            int m = i >> 3, k4 = i & 7;
            cp_async16(smem_u32(&dA[m * 36 + k4 * 4]),
                       &Wt[(size_t)m * 3072 + k0 + k4 * 4]);
        }
        float* dB = sB + s * 64 * 36;
        for (int i = t; i < 512; i += 256) {
            int n = i >> 3, k4 = i & 7;
            cp_async16(smem_u32(&dB[n * 36 + k4 * 4]),
                       &g_buf1[(size_t)(n0 + n) * 3072 + k0 + k4 * 4]);
        }
    };

    prefetch(kbase, 0);
    cp_commit();
    for (int i = 0; i < 48; i++) {
        int cur = i & 1;
        if (i + 1 < 48) {
            prefetch(kbase + (i + 1) * 32, cur ^ 1);
            cp_commit();
            cp_wait<1>();
        } else {
            cp_wait<0>();
        }
        __syncthreads();
        uint32_t aS = (uint32_t)cur * (128 * 36 * 4);
        uint32_t bS = (uint32_t)cur * (64 * 36 * 4);
        #pragma unroll
        for (int ks = 0; ks < 4; ks++) {
            int kb = ks * 8;
            uint32_t a0, a1, a2, a3;
            ldsm_x4(a0, a1, a2, a3, aaddr + aS + kb * 4);
            #pragma unroll
            for (int p = 0; p < 4; p++) {
                uint32_t b0, b1, b2, b3;
                ldsm_x4(b0, b1, b2, b3, baddr + bS + (p * 16 * 36 + kb) * 4);
                mma_tf32(acc[2 * p],     a0, a1, a2, a3, b0, b1);
                mma_tf32(acc[2 * p + 1], a0, a1, a2, a3, b2, b3);
            }
        }
        __syncthreads();
    }
    int m0 = warp * 16 + g, m1 = m0 + 8;
    float* fp = g_buf1 + FACC_OFF + (size_t)kh * BB * 128;
    #pragma unroll
    for (int j = 0; j < 8; j++) {
        long n = n0 + j * 8 + 2 * tg;
        fp[n * 128 + m0]       = acc[j][0];
        fp[(n + 1) * 128 + m0] = acc[j][1];
        fp[n * 128 + m1]       = acc[j][2];
        fp[(n + 1) * 128 + m1] = acc[j][3];
    }
}

// fc1 epilogue: feat = p0 + p1 + bias; g_buf2 = tf32r(relu(feat))
__global__ void k_fc1epi(const float* __restrict__ bias, float* __restrict__ feat_out) {
    size_t i = (size_t)blockIdx.x * 256 + threadIdx.x;   // B*128
    const float* p0 = g_buf1 + FACC_OFF;
    const float* p1 = p0 + (size_t)BB * 128;
    int m = (int)(i & 127);
    float f = p0[i] + p1[i] + bias[m];
    feat_out[i] = f;
    g_buf2[i] = tf32r(fmaxf(f, 0.f));
}

// ---------------- cls via mma: pre-rounded transposed weights ----------------
template<int MTOT, int STAGE, size_t CWOFF>
__global__ void __launch_bounds__(256, 3) k_clsmma(const float* __restrict__ bias,
                                                   float* __restrict__ outx) {
    const float* inb = (STAGE == 1) ? g_buf2 : g_buf1;
    const float* Wm  = g_buf1 + CWOFF;
    __shared__ float sA[128 * 36];
    __shared__ float sB[64 * 36];
    int t = threadIdx.x;
    int warp = t >> 5, lane = t & 31;
    int g = lane >> 2, tg = lane & 3;
    int mbase = blockIdx.y * 128;
    long n0 = (long)blockIdx.x * 64;
    float acc[8][4] = {};

    int atile = lane >> 3;
    int arow = warp * 16 + (lane & 7) + ((atile & 1) << 3);
    uint32_t aaddr = smem_u32(sA) + (uint32_t)(arow * 36 + (atile >> 1) * 4) * 4u;
    int brow = ((lane >> 4) << 3) + (lane & 7);
    uint32_t baddr = smem_u32(sB) + (uint32_t)(brow * 36 + ((lane >> 3) & 1) * 4) * 4u;

    for (int k0 = 0; k0 < 128; k0 += 32) {
        __syncthreads();
        for (int i = t; i < 128 * 8; i += 256) {
            int n = i >> 3, k4 = i & 7;
            *(float4*)&sA[n * 36 + k4 * 4] =
                *(const float4*)&Wm[(size_t)(mbase + n) * 128 + k0 + k4 * 4];
        }
        for (int i = t; i < 512; i += 256) {
            int n = i >> 3, k4 = i & 7;
            float4 v = *(const float4*)&inb[(size_t)(n0 + n) * 128 + k0 + k4 * 4];
            *(float4*)&sB[n * 36 + k4 * 4] = v;
        }
        __syncthreads();
        #pragma unroll
        for (int ks = 0; ks < 4; ks++) {
            int kb = ks * 8;
            uint32_t a0, a1, a2, a3;
            ldsm_x4(a0, a1, a2, a3, aaddr + kb * 4);
            #pragma unroll
            for (int p = 0; p < 4; p++) {
                uint32_t b0, b1, b2, b3;
                ldsm_x4(b0, b1, b2, b3, baddr + (p * 16 * 36 + kb) * 4);
                mma_tf32(acc[2 * p],     a0, a1, a2, a3, b0, b1);
                mma_tf32(acc[2 * p + 1], a0, a1, a2, a3, b2, b3);
            }
        }
    }
    int m0 = mbase + warp * 16 + g, m1 = m0 + 8;
    float bi0 = (m0 < MTOT) ? bias[m0] : 0.f;
    float bi1 = (m1 < MTOT) ? bias[m1] : 0.f;
    #pragma unroll
    for (int j = 0; j < 8; j++) {
        long b = n0 + j * 8 + 2 * tg;
        float f00 = acc[j][0] + bi0, f01 = acc[j][1] + bi0;
        float f10 = acc[j][2] + bi1, f11 = acc[j][3] + bi1;
        if (STAGE == 1) {
            f00 = tf32r(fmaxf(f00, 0.f)); f01 = tf32r(fmaxf(f01, 0.f));
            f10 = tf32r(fmaxf(f10, 0.f)); f11 = tf32r(fmaxf(f11, 0.f));
            g_buf1[b * 128 + m0] = f00; g_buf1[(b + 1) * 128 + m0] = f01;
            g_buf1[b * 128 + m1] = f10; g_buf1[(b + 1) * 128 + m1] = f11;
        } else {
            if (m0 < MTOT) { outx[b * MTOT + m0] = f00; outx[(b + 1) * MTOT + m0] = f01; }
            if (m1 < MTOT) { outx[b * MTOT + m1] = f10; outx[(b + 1) * MTOT + m1] = f11; }
        }
    }
}

// ---------------- launch ------------------------------------------------------
extern "C" void kernel_launch(void* const* d_in, const int* in_sizes, int n_in,
                              void* d_out, int out_size) {
    const float* src     = (const float*)d_in[0];
    const int*   ei      = (const int*)d_in[1];
    const float* gcn1_w  = (const float*)d_in[2];
    const float* gcn1_b  = (const float*)d_in[3];
    const float* gcn2_w  = (const float*)d_in[4];
    const float* gcn2_b  = (const float*)d_in[5];
    const float* conv1_w = (const float*)d_in[6];
    const float* conv1_b = (const float*)d_in[7];
    const float* conv2_w = (const float*)d_in[8];
    const float* conv2_b = (const float*)d_in[9];
    const float* conv3_w = (const float*)d_in[10];
    const float* conv3_b = (const float*)d_in[11];
    const float* fc1_w   = (const float*)d_in[12];
    const float* fc1_b   = (const float*)d_in[13];
    const float* cls1_w  = (const float*)d_in[14];
    const float* cls1_b  = (const float*)d_in[15];
    const float* cls2_w  = (const float*)d_in[16];
    const float* cls2_b  = (const float*)d_in[17];

    int ne = in_sizes[1] / 2;

    float* out   = (float*)d_out;
    float* out_x = out;                          // [B,210]
    float* out_f = out + (size_t)BB * 210;       // [B,128]

    const int GCNB_SMEM = (64 * 20 + 32 * 68 + 128 * 20 + 128 * 68 + 64) * 4;
    const int CONV_SMEM = 2 * 192 * 36 * 4;      // 55296
    const int FC1_SMEM  = 2 * 192 * 36 * 4;      // 55296

    cudaFuncSetAttribute(k_gcnBmma, cudaFuncAttributeMaxDynamicSharedMemorySize, GCNB_SMEM);
    cudaFuncSetAttribute(k_convmma<64, 4, 2, 224, 32, 48, 96, 3, 64, 0, CW1_OFF>,
                         cudaFuncAttributeMaxDynamicSharedMemorySize, CONV_SMEM);
    cudaFuncSetAttribute(k_convmma<128, 8, 1, 320, 64, 24, 48, 2, 128, 1, CW2_OFF>,
                         cudaFuncAttributeMaxDynamicSharedMemorySize, CONV_SMEM);
    cudaFuncSetAttribute(k_convmma<128, 8, 1, 384, 128, 12, 24, 1, 256, 0, CW3_OFF>,
                         cudaFuncAttributeMaxDynamicSharedMemorySize, CONV_SMEM);
    cudaFuncSetAttribute(k_fc1mma, cudaFuncAttributeMaxDynamicSharedMemorySize, FC1_SMEM);

    k_build_adj<<<1, 256>>>(ei, ne);
    k_prep<<<1536, 256>>>(fc1_w, conv1_w, conv2_w, conv3_w, cls1_w, cls2_w);

    k_gcnAmma<<<2048, 256>>>(src);
    k_gcnBmma<<<BB * 96 / 128, 256, GCNB_SMEM>>>(gcn1_w, gcn1_b, gcn2_w);
    k_gcnCmma<<<4096, 256>>>(gcn2_b);

    k_convmma<64, 4, 2, 224, 32, 48, 96, 3, 64, 0, CW1_OFF>
        <<<dim3(3072, 1), 256, CONV_SMEM>>>(conv1_b);
    k_convmma<128, 8, 1, 320, 64, 24, 48, 2, 128, 1, CW2_OFF>
        <<<dim3(3072, 1), 256, CONV_SMEM>>>(conv2_b);
    k_convmma<128, 8, 1, 384, 128, 12, 24, 1, 256, 0, CW3_OFF>
        <<<dim3(1536, 2), 256, CONV_SMEM>>>(conv3_b);

    k_fc1mma<<<dim3(128, 2), 256, FC1_SMEM>>>();
    k_fc1epi<<<BB * 128 / 256, 256>>>(fc1_b, out_f);
    k_clsmma<128, 1, CWC1_OFF><<<dim3(128, 1), 256>>>(cls1_b, nullptr);
    k_clsmma<210, 2, CWC2_OFF><<<dim3(128, 2), 256>>>(cls2_b, out_x);
}

// round 17
// speedup vs baseline: 1.0986x; 1.0885x over previous
#include <cuda_runtime.h>
#include <cstdint>
#include <math.h>

#define BB 8192

__device__ __forceinline__ float tf32r(float x) {
    uint32_t u;
    asm("cvt.rna.tf32.f32 %0, %1;" : "=r"(u) : "f"(x));
    return __uint_as_float(u);
}

__device__ __forceinline__ void mma_tf32(float c[4],
                                         uint32_t a0, uint32_t a1, uint32_t a2, uint32_t a3,
                                         uint32_t b0, uint32_t b1) {
    asm volatile(
        "mma.sync.aligned.m16n8k8.row.col.f32.tf32.tf32.f32 "
        "{%0,%1,%2,%3}, {%4,%5,%6,%7}, {%8,%9}, {%0,%1,%2,%3};"
        : "+f"(c[0]), "+f"(c[1]), "+f"(c[2]), "+f"(c[3])
        : "r"(a0), "r"(a1), "r"(a2), "r"(a3), "r"(b0), "r"(b1));
}

__device__ __forceinline__ void ldsm_x4(uint32_t& r0, uint32_t& r1, uint32_t& r2, uint32_t& r3,
                                        uint32_t addr) {
    asm volatile("ldmatrix.sync.aligned.m8n8.x4.shared.b16 {%0,%1,%2,%3}, [%4];"
                 : "=r"(r0), "=r"(r1), "=r"(r2), "=r"(r3) : "r"(addr));
}

__device__ __forceinline__ void ldsm_x2(uint32_t& r0, uint32_t& r1, uint32_t addr) {
    asm volatile("ldmatrix.sync.aligned.m8n8.x2.shared.b16 {%0,%1}, [%2];"
                 : "=r"(r0), "=r"(r1) : "r"(addr));
}

__device__ __forceinline__ uint32_t smem_u32(const void* p) {
    return (uint32_t)__cvta_generic_to_shared(p);
}

__device__ __forceinline__ void cp_async16(uint32_t dst, const void* src) {
    asm volatile("cp.async.cg.shared.global [%0], [%1], 16;" :: "r"(dst), "l"(src));
}
__device__ __forceinline__ void cp_async16z(uint32_t dst, const void* src, bool valid) {
    int sz = valid ? 16 : 0;
    asm volatile("cp.async.cg.shared.global [%0], [%1], 16, %2;"
                 :: "r"(dst), "l"(src), "r"(sz));
}
__device__ __forceinline__ void cp_commit() {
    asm volatile("cp.async.commit_group;");
}
template<int N>
__device__ __forceinline__ void cp_wait() {
    asm volatile("cp.async.wait_group %0;" :: "n"(N));
}

// ---------------- scratch ----------------------------------------------------
__device__ float g_A[96 * 96];
__device__ float g_Aq[128 * 96];
__device__ float g_buf1[(size_t)BB * 6144];
__device__ float g_buf2[(size_t)BB * 3072];

constexpr size_t FACC_OFF = (size_t)BB * 3072;
constexpr size_t WT_OFF   = (size_t)BB * 4608;
constexpr size_t CW1_OFF  = WT_OFF + 393216;
constexpr size_t CW2_OFF  = CW1_OFF + 14336;
constexpr size_t CW3_OFF  = CW2_OFF + 40960;
constexpr size_t CWC1_OFF = CW3_OFF + 98304;
constexpr size_t CWC2_OFF = CWC1_OFF + 16384;

// ---------------- adjacency: build + round + pad ------------------------------
__global__ void k_build_adj(const int* __restrict__ ei, int ne) {
    __shared__ float deg[96];
    __shared__ float dinv[96];
    int t = threadIdx.x;
    if (t < 96) deg[t] = 0.f;
    for (int i = t; i < 9216; i += 256) g_A[i] = 0.f;
    __syncthreads();
    for (int e = t; e < ne; e += 256) atomicAdd(&deg[ei[e]], 1.0f);
    if (t < 96) atomicAdd(&deg[t], 1.0f);
    __syncthreads();
    if (t < 96) dinv[t] = 1.0f / sqrtf(fmaxf(deg[t], 1e-12f));
    __syncthreads();
    for (int e = t; e < ne; e += 256) {
        int r = ei[e], c = ei[ne + e];
        atomicAdd(&g_A[r * 96 + c], dinv[r] * dinv[c]);
    }
    if (t < 96) atomicAdd(&g_A[t * 96 + t], dinv[t] * dinv[t]);
    __syncthreads();
    for (int i = t; i < 128 * 96; i += 256)
        g_Aq[i] = (i < 9216) ? tf32r(g_A[i]) : 0.f;
}

// ---------------- merged weight prep -----------------------------------------
__global__ void k_prep(const float* __restrict__ W, const float* __restrict__ w1,
                       const float* __restrict__ w2, const float* __restrict__ w3,
                       const float* __restrict__ c1, const float* __restrict__ c2) {
    int i = blockIdx.x * 256 + threadIdx.x;
    if (i < 393216) {
        int m = i / 3072, kn = i % 3072;
        int p = kn >> 8, c = kn & 255;
        g_buf1[WT_OFF + i] = tf32r(W[(size_t)(c * 12 + p) * 128 + m]);
    }
    if (i < 14336) {
        int o = i / 224, r = i % 224, ic = r / 7, kk = r % 7;
        g_buf1[CW1_OFF + o * 224 + kk * 32 + ic] = tf32r(w1[i]);
    }
    if (i < 40960) {
        int o = i / 320, r = i % 320, ic = r / 5, kk = r % 5;
        g_buf1[CW2_OFF + o * 320 + kk * 64 + ic] = tf32r(w2[i]);
    }
    if (i < 98304) {
        int o = i / 384, r = i % 384, ic = r / 3, kk = r % 3;
        g_buf1[CW3_OFF + o * 384 + kk * 128 + ic] = tf32r(w3[i]);
    }
    if (i < 16384) {
        int m = i >> 7, k = i & 127;
        g_buf1[CWC1_OFF + i] = tf32r(c1[(size_t)k * 128 + m]);
    }
    if (i < 32768) {
        int m = i >> 7, k = i & 127;
        g_buf1[CWC2_OFF + i] = (m < 210) ? tf32r(c2[(size_t)k * 210 + m]) : 0.f;
    }
}

// ---------------- gcnA via mma: Y[n,(b,c)] = A@Xq ----------------------------
__global__ void __launch_bounds__(256, 3) k_gcnAmma(const float* __restrict__ src) {
    __shared__ float sA[128 * 36];
    __shared__ float sB[64 * 36];
    int t = threadIdx.x;
    int warp = t >> 5, lane = t & 31;
    int g = lane >> 2, tg = lane & 3;
    long n0 = (long)blockIdx.x * 64;
    float acc[8][4] = {};

    int atile = lane >> 3;
    int arow = warp * 16 + (lane & 7) + ((atile & 1) << 3);
    uint32_t aaddr = smem_u32(sA) + (uint32_t)(arow * 36 + (atile >> 1) * 4) * 4u;
    int brow = ((lane >> 4) << 3) + (lane & 7);
    uint32_t baddr = smem_u32(sB) + (uint32_t)(brow * 36 + ((lane >> 3) & 1) * 4) * 4u;

    for (int k0 = 0; k0 < 96; k0 += 32) {
        __syncthreads();
        for (int i = t; i < 128 * 8; i += 256) {
            int m = i >> 3, k4 = i & 7;
            *(float4*)&sA[m * 36 + k4 * 4] = *(const float4*)&g_Aq[m * 96 + k0 + k4 * 4];
        }
        for (int i = t; i < 64 * 8; i += 256) {
            int n = i >> 3, q = i & 7;
            long col = n0 + n;
            int b = (int)(col >> 4), c = (int)(col & 15);
            float4 v = *(const float4*)&src[(size_t)b * 1536 + c * 96 + k0 + q * 4];
            v.x = tf32r(v.x); v.y = tf32r(v.y); v.z = tf32r(v.z); v.w = tf32r(v.w);
            *(float4*)&sB[n * 36 + q * 4] = v;
        }
        __syncthreads();
        #pragma unroll
        for (int ks = 0; ks < 4; ks++) {
            int kb = ks * 8;
            uint32_t a0, a1, a2, a3;
            ldsm_x4(a0, a1, a2, a3, aaddr + kb * 4);
            #pragma unroll
            for (int p = 0; p < 4; p++) {
                uint32_t b0, b1, b2, b3;
                ldsm_x4(b0, b1, b2, b3, baddr + (p * 16 * 36 + kb) * 4);
                mma_tf32(acc[2 * p],     a0, a1, a2, a3, b0, b1);
                mma_tf32(acc[2 * p + 1], a0, a1, a2, a3, b2, b3);
            }
        }
    }
    int m0 = warp * 16 + g, m1 = m0 + 8;
    if (m0 < 96) {
        #pragma unroll
        for (int j = 0; j < 8; j++) {
            long nc = n0 + j * 8 + 2 * tg;
            int b = (int)(nc >> 4), c = (int)(nc & 15);
            float* yb = g_buf1 + (size_t)b * 1536;
            yb[m0 * 16 + c]     = acc[j][0];
            yb[m0 * 16 + c + 1] = acc[j][1];
            yb[m1 * 16 + c]     = acc[j][2];
            yb[m1 * 16 + c + 1] = acc[j][3];
        }
    }
}

// ---------------- fused gcnB+gcnC: 2 batches/block, T never leaves smem ------
// Phase 1 (x2 halves): sY <- Yq(batch); H=tf32r(relu(W1^T@Y+b1)); T=W2^T@H ->
// sTt[half*32+g][node] (tf32r). Phase 2: out = relu(A@T + b2) (gcnC stage).
__global__ void __launch_bounds__(256, 3) k_gcnBC(const float* __restrict__ W1,
                                                  const float* __restrict__ b1,
                                                  const float* __restrict__ W2,
                                                  const float* __restrict__ b2) {
    extern __shared__ float sm[];
    float* sTt = sm;              // [64][100] = 6400
    float* sW2 = sTt + 6400;      // [32][68]  = 2176
    float* sB1 = sW2 + 2176;      // [64]
    float* sR  = sB1 + 64;        // union region (9728 floats)
    float* sW1 = sR;              // [64][20]  = 1280   (phase 1)
    float* sY  = sR + 1280;       // [96][20]  = 1920   (phase 1)
    float* sH  = sR + 3200;       // [96][68]  = 6528   (phase 1)
    float* sA  = sR;              // [128][36] = 4608   (phase 2, aliases)

    int t = threadIdx.x;
    int warp = t >> 5, lane = t & 31;
    int g = lane >> 2, tg = lane & 3;
    int b0 = blockIdx.x * 2;
    long n0 = (long)blockIdx.x * 64;

    // weights once
    for (int i = t; i < 1024; i += 256) {
        int c = i >> 6, f = i & 63;
        sW1[f * 20 + c] = tf32r(W1[i]);
    }
    for (int i = t; i < 2048; i += 256) {
        int f = i >> 5, gg = i & 31;
        sW2[gg * 68 + f] = tf32r(W2[i]);
    }
    if (t < 64) sB1[t] = b1[t];
    __syncthreads();

    for (int half = 0; half < 2; half++) {
        // load Y rows of batch b0+half (96 rows x 16), tf32-rounded
        const float* yb = g_buf1 + (size_t)(b0 + half) * 1536;
        for (int i = t; i < 96 * 4; i += 256) {
            int r = i >> 2, c4 = i & 3;
            float4 v = *(const float4*)&yb[r * 16 + c4 * 4];
            v.x = tf32r(v.x); v.y = tf32r(v.y); v.z = tf32r(v.z); v.w = tf32r(v.w);
            *(float4*)&sY[r * 20 + c4 * 4] = v;
        }
        __syncthreads();

        {   // stage 1: H[64f x 96rows] = W1^T @ Yq ; M=64 (wm=warp&3), N=96 (wn 2x48)
            int wm = warp & 3, wn = warp >> 2;
            int atile = lane >> 3;
            int arow = wm * 16 + (lane & 7) + ((atile & 1) << 3);
            uint32_t aaddr = smem_u32(sW1) + (uint32_t)(arow * 20 + (atile >> 1) * 4) * 4u;
            int brow = wn * 48 + ((lane >> 4) << 3) + (lane & 7);
            uint32_t baddr = smem_u32(sY) + (uint32_t)(brow * 20 + ((lane >> 3) & 1) * 4) * 4u;

            float acc[6][4] = {};
            #pragma unroll
            for (int ks = 0; ks < 2; ks++) {
                int kb = ks * 8;
                uint32_t a0, a1, a2, a3;
                ldsm_x4(a0, a1, a2, a3, aaddr + kb * 4);
                #pragma unroll
                for (int p = 0; p < 3; p++) {
                    uint32_t bb0, bb1, bb2, bb3;
                    ldsm_x4(bb0, bb1, bb2, bb3, baddr + (p * 16 * 20 + kb) * 4);
                    mma_tf32(acc[2 * p],     a0, a1, a2, a3, bb0, bb1);
                    mma_tf32(acc[2 * p + 1], a0, a1, a2, a3, bb2, bb3);
                }
            }
            int m0 = wm * 16 + g, m1 = m0 + 8;
            float bi0 = sB1[m0], bi1 = sB1[m1];
            __syncthreads();                       // sY read done before sH write? distinct buffers; sync for safety order with next half reload
            #pragma unroll
            for (int j = 0; j < 6; j++) {
                int r = wn * 48 + j * 8 + 2 * tg;
                sH[r * 68 + m0]       = tf32r(fmaxf(acc[j][0] + bi0, 0.f));
                sH[(r + 1) * 68 + m0] = tf32r(fmaxf(acc[j][1] + bi0, 0.f));
                sH[r * 68 + m1]       = tf32r(fmaxf(acc[j][2] + bi1, 0.f));
                sH[(r + 1) * 68 + m1] = tf32r(fmaxf(acc[j][3] + bi1, 0.f));
            }
        }
        __syncthreads();

        {   // stage 2: T[32g x 96rows] = W2^T @ H ; M=32 (wm=warp&1), N=96 (wn 4x24)
            int wm = warp & 1, wn = warp >> 1;
            int atile = lane >> 3;
            int arow = wm * 16 + (lane & 7) + ((atile & 1) << 3);
            uint32_t aaddr = smem_u32(sW2) + (uint32_t)(arow * 68 + (atile >> 1) * 4) * 4u;
            int browp = wn * 24 + ((lane >> 4) << 3) + (lane & 7);          // x4 pair rows
            uint32_t baddrp = smem_u32(sH) + (uint32_t)(browp * 68 + ((lane >> 3) & 1) * 4) * 4u;
            int brows = wn * 24 + 16 + (lane & 7);                           // x2 single tile
            uint32_t baddrs = smem_u32(sH) + (uint32_t)(brows * 68 + ((lane >> 3) & 1) * 4) * 4u;

            float acc[3][4] = {};
            #pragma unroll
            for (int ks = 0; ks < 8; ks++) {
                int kb = ks * 8;
                uint32_t a0, a1, a2, a3;
                ldsm_x4(a0, a1, a2, a3, aaddr + kb * 4);
                uint32_t bb0, bb1, bb2, bb3;
                ldsm_x4(bb0, bb1, bb2, bb3, baddrp + kb * 4);
                mma_tf32(acc[0], a0, a1, a2, a3, bb0, bb1);
                mma_tf32(acc[1], a0, a1, a2, a3, bb2, bb3);
                uint32_t sb0, sb1;
                ldsm_x2(sb0, sb1, baddrs + kb * 4);
                mma_tf32(acc[2], a0, a1, a2, a3, sb0, sb1);
            }
            int m0 = wm * 16 + g, m1 = m0 + 8;
            #pragma unroll
            for (int j = 0; j < 3; j++) {
                int r = wn * 24 + j * 8 + 2 * tg;
                sTt[(half * 32 + m0) * 100 + r]     = tf32r(acc[j][0]);
                sTt[(half * 32 + m0) * 100 + r + 1] = tf32r(acc[j][1]);
                sTt[(half * 32 + m1) * 100 + r]     = tf32r(acc[j][2]);
                sTt[(half * 32 + m1) * 100 + r + 1] = tf32r(acc[j][3]);
            }
        }
        __syncthreads();
    }

    // Phase 2: out = relu(A @ T + b2) — stage3, B fragments straight from sTt
    {
        float acc[8][4] = {};
        int atile = lane >> 3;
        int arow = warp * 16 + (lane & 7) + ((atile & 1) << 3);
        uint32_t aaddr = smem_u32(sA) + (uint32_t)(arow * 36 + (atile >> 1) * 4) * 4u;
        int brow = ((lane >> 4) << 3) + (lane & 7);
        uint32_t baddr = smem_u32(sTt) + (uint32_t)(brow * 100 + ((lane >> 3) & 1) * 4) * 4u;

        for (int k0 = 0; k0 < 96; k0 += 32) {
            __syncthreads();
            for (int i = t; i < 128 * 8; i += 256) {
                int m = i >> 3, k4 = i & 7;
                *(float4*)&sA[m * 36 + k4 * 4] = *(const float4*)&g_Aq[m * 96 + k0 + k4 * 4];
            }
            __syncthreads();
            #pragma unroll
            for (int ks = 0; ks < 4; ks++) {
                int kb = ks * 8;
                uint32_t a0, a1, a2, a3;
                ldsm_x4(a0, a1, a2, a3, aaddr + kb * 4);
                #pragma unroll
                for (int p = 0; p < 4; p++) {
                    uint32_t bb0, bb1, bb2, bb3;
                    ldsm_x4(bb0, bb1, bb2, bb3, baddr + (p * 16 * 100 + k0 + kb) * 4);
                    mma_tf32(acc[2 * p],     a0, a1, a2, a3, bb0, bb1);
                    mma_tf32(acc[2 * p + 1], a0, a1, a2, a3, bb2, bb3);
                }
            }
        }
        int m0 = warp * 16 + g, m1 = m0 + 8;
        if (m0 < 96) {
            #pragma unroll
            for (int j = 0; j < 8; j++) {
                long nc = n0 + j * 8 + 2 * tg;
                int b = (int)(nc >> 5), gg = (int)(nc & 31);
                float bg0 = b2[gg], bg1 = b2[gg + 1];
                float* ob = g_buf2 + (size_t)b * 3072;
                ob[m0 * 32 + gg]     = tf32r(fmaxf(acc[j][0] + bg0, 0.f));
                ob[m0 * 32 + gg + 1] = tf32r(fmaxf(acc[j][1] + bg1, 0.f));
                ob[m1 * 32 + gg]     = tf32r(fmaxf(acc[j][2] + bg0, 0.f));
                ob[m1 * 32 + gg + 1] = tf32r(fmaxf(acc[j][3] + bg1, 0.f));
            }
        }
    }
}

// ---------------- conv implicit GEMM, channel-last, cp.async 16B -------------
template<int M_BLK, int WM, int WN, int KTOT, int IC, int NPOS, int LIN, int PAD,
         int OC, int IO, size_t WOFF>
__global__ void __launch_bounds__(256, 3) k_convmma(const float* __restrict__ bias) {
    const float* w  = g_buf1 + WOFF;
    const float* in = (IO == 0) ? g_buf2 : g_buf1;
    float* outp     = (IO == 0) ? g_buf1 : g_buf2;
    constexpr int N_BLK = WN * 64;
    extern __shared__ float smd[];
    float* sA = smd;
    float* sB = smd + 2 * M_BLK * 36;
    int t = threadIdx.x;
    int warp = t >> 5, lane = t & 31;
    int g = lane >> 2, tg = lane & 3;
    int wm = warp % WM, wn = warp / WM;
    int mbase = blockIdx.y * M_BLK;
    long n0 = (long)blockIdx.x * N_BLK;

    float acc[8][4] = {};

    int atile = lane >> 3;
    int arow = wm * 16 + (lane & 7) + ((atile & 1) << 3);
    uint32_t aaddr = smem_u32(sA) + (uint32_t)(arow * 36 + (atile >> 1) * 4) * 4u;
    int brow = wn * 64 + ((lane >> 4) << 3) + (lane & 7);
    uint32_t baddr = smem_u32(sB) + (uint32_t)(brow * 36 + ((lane >> 3) & 1) * 4) * 4u;

    auto prefetch = [&](int k0, int s) {
        float* dA = sA + s * M_BLK * 36;
        for (int i = t; i < M_BLK * 8; i += 256) {
            int m = i >> 3, k4 = i & 7;
            cp_async16(smem_u32(&dA[m * 36 + k4 * 4]),
                       &w[(size_t)(mbase + m) * KTOT + k0 + k4 * 4]);
        }
        int kk = k0 / IC, ic0 = k0 % IC;
        float* dB = sB + s * N_BLK * 36;
        for (int i = t; i < N_BLK * 8; i += 256) {
            int n = i >> 3, q = i & 7;
            long ng = n0 + n;
            int b = (int)(ng / NPOS), p = (int)(ng % NPOS);
            int pos = p * 2 + kk - PAD;
            bool valid = (pos >= 0 && pos < LIN);
            const float* sp = &in[(size_t)b * 3072 + (valid ? pos : 0) * IC + ic0 + q * 4];
            cp_async16z(smem_u32(&dB[n * 36 + q * 4]), sp, valid);
        }
    };

    constexpr int NCH = KTOT / 32;
    prefetch(0, 0);
    cp_commit();
    for (int i = 0; i < NCH; i++) {
        int cur = i & 1;
        if (i + 1 < NCH) {
            prefetch((i + 1) * 32, cur ^ 1);
            cp_commit();
            cp_wait<1>();
        } else {
            cp_wait<0>();
        }
        __syncthreads();
        uint32_t aS = (uint32_t)cur * (M_BLK * 36 * 4);
        uint32_t bS = (uint32_t)cur * (N_BLK * 36 * 4);
        #pragma unroll
        for (int ks = 0; ks < 4; ks++) {
            int kb = ks * 8;
            uint32_t a0, a1, a2, a3;
            ldsm_x4(a0, a1, a2, a3, aaddr + aS + kb * 4);
            #pragma unroll
            for (int p = 0; p < 4; p++) {
                uint32_t b0, b1, b2, b3;
                ldsm_x4(b0, b1, b2, b3, baddr + bS + (p * 16 * 36 + kb) * 4);
                mma_tf32(acc[2 * p],     a0, a1, a2, a3, b0, b1);
                mma_tf32(acc[2 * p + 1], a0, a1, a2, a3, b2, b3);
            }
        }
        __syncthreads();
    }
    int m0 = mbase + wm * 16 + g;
    int m1 = m0 + 8;
    float bi0 = bias[m0], bi1 = bias[m1];
    #pragma unroll
    for (int j = 0; j < 8; j++) {
        long nc = n0 + wn * 64 + j * 8 + 2 * tg;
        int b = (int)(nc / NPOS), p = (int)(nc % NPOS);
        float* ob = outp + (size_t)b * 3072;
        ob[p * OC + m0]       = tf32r(fmaxf(acc[j][0] + bi0, 0.f));
        ob[(p + 1) * OC + m0] = tf32r(fmaxf(acc[j][1] + bi0, 0.f));
        ob[p * OC + m1]       = tf32r(fmaxf(acc[j][2] + bi1, 0.f));
        ob[(p + 1) * OC + m1] = tf32r(fmaxf(acc[j][3] + bi1, 0.f));
    }
}

// ---------------- fc1 via mma, split-K x2, partials to FACC ------------------
__global__ void __launch_bounds__(256, 3) k_fc1mma() {
    const float* Wt = g_buf1 + WT_OFF;
    extern __shared__ float smd[];
    float* sA = smd;
    float* sB = smd + 2 * 128 * 36;
    int t = threadIdx.x;
    int warp = t >> 5, lane = t & 31;
    int g = lane >> 2, tg = lane & 3;
    long n0 = (long)blockIdx.x * 64;
    int kh = blockIdx.y;
    int kbase = kh * 1536;
    float acc[8][4] = {};

    int atile = lane >> 3;
    int arow = warp * 16 + (lane & 7) + ((atile & 1) << 3);
    uint32_t aaddr = smem_u32(sA) + (uint32_t)(arow * 36 + (atile >> 1) * 4) * 4u;
    int brow = ((lane >> 4) << 3) + (lane & 7);
    uint32_t baddr = smem_u32(sB) + (uint32_t)(brow * 36 + ((lane >> 3) & 1) * 4) * 4u;

    auto prefetch = [&](int k0, int s) {
        float* dA = sA + s * 128 * 36;
        for (int i = t; i < 1024; i += 256) {
            int m = i >> 3, k4 = i & 7;
            cp_async16(smem_u32(&dA[m * 36 + k4 * 4]),
                       &Wt[(size_t)m * 3072 + k0 + k4 * 4]);
        }
        float* dB = sB + s * 64 * 36;
        for (int i = t; i < 512; i += 256) {
            int n = i >> 3, k4 = i & 7;
            cp_async16(smem_u32(&dB[n * 36 + k4 * 4]),
                       &g_buf1[(size_t)(n0 + n) * 3072 + k0 + k4 * 4]);
        }
    };

    prefetch(kbase, 0);
    cp_commit();
    for (int i = 0; i < 48; i++) {
        int cur = i & 1;
        if (i + 1 < 48) {
            prefetch(kbase + (i + 1) * 32, cur ^ 1);
            cp_commit();
            cp_wait<1>();
        } else {
            cp_wait<0>();
        }
        __syncthreads();
        uint32_t aS = (uint32_t)cur * (128 * 36 * 4);
        uint32_t bS = (uint32_t)cur * (64 * 36 * 4);
        #pragma unroll
        for (int ks = 0; ks < 4; ks++) {
            int kb = ks * 8;
            uint32_t a0, a1, a2, a3;
            ldsm_x4(a0, a1, a2, a3, aaddr + aS + kb * 4);
            #pragma unroll
            for (int p = 0; p < 4; p++) {
                uint32_t b0, b1, b2, b3;
                ldsm_x4(b0, b1, b2, b3, baddr + bS + (p * 16 * 36 + kb) * 4);
                mma_tf32(acc[2 * p],     a0, a1, a2, a3, b0, b1);
                mma_tf32(acc[2 * p + 1], a0, a1, a2, a3, b2, b3);
            }
        }
        __syncthreads();
    }
    int m0 = warp * 16 + g, m1 = m0 + 8;
    float* fp = g_buf1 + FACC_OFF + (size_t)kh * BB * 128;
    #pragma unroll
    for (int j = 0; j < 8; j++) {
        long n = n0 + j * 8 + 2 * tg;
        fp[n * 128 + m0]       = acc[j][0];
        fp[(n + 1) * 128 + m0] = acc[j][1];
        fp[n * 128 + m1]       = acc[j][2];
        fp[(n + 1) * 128 + m1] = acc[j][3];
    }
}

__global__ void k_fc1epi(const float* __restrict__ bias, float* __restrict__ feat_out) {
    size_t i = (size_t)blockIdx.x * 256 + threadIdx.x;
    const float* p0 = g_buf1 + FACC_OFF;
    const float* p1 = p0 + (size_t)BB * 128;
    int m = (int)(i & 127);
    float f = p0[i] + p1[i] + bias[m];
    feat_out[i] = f;
    g_buf2[i] = tf32r(fmaxf(f, 0.f));
}

// ---------------- cls via mma ------------------------------------------------
template<int MTOT, int STAGE, size_t CWOFF>
__global__ void __launch_bounds__(256, 3) k_clsmma(const float* __restrict__ bias,
                                                   float* __restrict__ outx) {
    const float* inb = (STAGE == 1) ? g_buf2 : g_buf1;
    const float* Wm  = g_buf1 + CWOFF;
    __shared__ float sA[128 * 36];
    __shared__ float sB[64 * 36];
    int t = threadIdx.x;
    int warp = t >> 5, lane = t & 31;
    int g = lane >> 2, tg = lane & 3;
    int mbase = blockIdx.y * 128;
    long n0 = (long)blockIdx.x * 64;
    float acc[8][4] = {};

    int atile = lane >> 3;
    int arow = warp * 16 + (lane & 7) + ((atile & 1) << 3);
    uint32_t aaddr = smem_u32(sA) + (uint32_t)(arow * 36 + (atile >> 1) * 4) * 4u;
    int brow = ((lane >> 4) << 3) + (lane & 7);
    uint32_t baddr = smem_u32(sB) + (uint32_t)(brow * 36 + ((lane >> 3) & 1) * 4) * 4u;

    for (int k0 = 0; k0 < 128; k0 += 32) {
        __syncthreads();
        for (int i = t; i < 128 * 8; i += 256) {
            int n = i >> 3, k4 = i & 7;
            *(float4*)&sA[n * 36 + k4 * 4] =
                *(const float4*)&Wm[(size_t)(mbase + n) * 128 + k0 + k4 * 4];
        }
        for (int i = t; i < 512; i += 256) {
            int n = i >> 3, k4 = i & 7;
            float4 v = *(const float4*)&inb[(size_t)(n0 + n) * 128 + k0 + k4 * 4];
            *(float4*)&sB[n * 36 + k4 * 4] = v;
        }
        __syncthreads();
        #pragma unroll
        for (int ks = 0; ks < 4; ks++) {
            int kb = ks * 8;
            uint32_t a0, a1, a2, a3;
            ldsm_x4(a0, a1, a2, a3, aaddr + kb * 4);
            #pragma unroll
            for (int p = 0; p < 4; p++) {
                uint32_t b0, b1, b2, b3;
                ldsm_x4(b0, b1, b2, b3, baddr + (p * 16 * 36 + kb) * 4);
                mma_tf32(acc[2 * p],     a0, a1, a2, a3, b0, b1);
                mma_tf32(acc[2 * p + 1], a0, a1, a2, a3, b2, b3);
            }
        }
    }
    int m0 = mbase + warp * 16 + g, m1 = m0 + 8;
    float bi0 = (m0 < MTOT) ? bias[m0] : 0.f;
    float bi1 = (m1 < MTOT) ? bias[m1] : 0.f;
    #pragma unroll
    for (int j = 0; j < 8; j++) {
        long b = n0 + j * 8 + 2 * tg;
        float f00 = acc[j][0] + bi0, f01 = acc[j][1] + bi0;
        float f10 = acc[j][2] + bi1, f11 = acc[j][3] + bi1;
        if (STAGE == 1) {
            f00 = tf32r(fmaxf(f00, 0.f)); f01 = tf32r(fmaxf(f01, 0.f));
            f10 = tf32r(fmaxf(f10, 0.f)); f11 = tf32r(fmaxf(f11, 0.f));
            g_buf1[b * 128 + m0] = f00; g_buf1[(b + 1) * 128 + m0] = f01;
            g_buf1[b * 128 + m1] = f10; g_buf1[(b + 1) * 128 + m1] = f11;
        } else {
            if (m0 < MTOT) { outx[b * MTOT + m0] = f00; outx[(b + 1) * MTOT + m0] = f01; }
            if (m1 < MTOT) { outx[b * MTOT + m1] = f10; outx[(b + 1) * MTOT + m1] = f11; }
        }
    }
}

// ---------------- launch ------------------------------------------------------
extern "C" void kernel_launch(void* const* d_in, const int* in_sizes, int n_in,
                              void* d_out, int out_size) {
    const float* src     = (const float*)d_in[0];
    const int*   ei      = (const int*)d_in[1];
    const float* gcn1_w  = (const float*)d_in[2];
    const float* gcn1_b  = (const float*)d_in[3];
    const float* gcn2_w  = (const float*)d_in[4];
    const float* gcn2_b  = (const float*)d_in[5];
    const float* conv1_w = (const float*)d_in[6];
    const float* conv1_b = (const float*)d_in[7];
    const float* conv2_w = (const float*)d_in[8];
    const float* conv2_b = (const float*)d_in[9];
    const float* conv3_w = (const float*)d_in[10];
    const float* conv3_b = (const float*)d_in[11];
    const float* fc1_w   = (const float*)d_in[12];
    const float* fc1_b   = (const float*)d_in[13];
    const float* cls1_w  = (const float*)d_in[14];
    const float* cls1_b  = (const float*)d_in[15];
    const float* cls2_w  = (const float*)d_in[16];
    const float* cls2_b  = (const float*)d_in[17];

    int ne = in_sizes[1] / 2;

    float* out   = (float*)d_out;
    float* out_x = out;                          // [B,210]
    float* out_f = out + (size_t)BB * 210;       // [B,128]

    const int GCNBC_SMEM = (6400 + 2176 + 64 + 9728) * 4;   // 73472
    const int CONV_SMEM  = 2 * 192 * 36 * 4;                // 55296
    const int FC1_SMEM   = 2 * 192 * 36 * 4;                // 55296

    cudaFuncSetAttribute(k_gcnBC, cudaFuncAttributeMaxDynamicSharedMemorySize, GCNBC_SMEM);
    cudaFuncSetAttribute(k_convmma<64, 4, 2, 224, 32, 48, 96, 3, 64, 0, CW1_OFF>,
                         cudaFuncAttributeMaxDynamicSharedMemorySize, CONV_SMEM);
    cudaFuncSetAttribute(k_convmma<128, 8, 1, 320, 64, 24, 48, 2, 128, 1, CW2_OFF>,
                         cudaFuncAttributeMaxDynamicSharedMemorySize, CONV_SMEM);
    cudaFuncSetAttribute(k_convmma<128, 8, 1, 384, 128, 12, 24, 1, 256, 0, CW3_OFF>,
                         cudaFuncAttributeMaxDynamicSharedMemorySize, CONV_SMEM);
    cudaFuncSetAttribute(k_fc1mma, cudaFuncAttributeMaxDynamicSharedMemorySize, FC1_SMEM);

    k_build_adj<<<1, 256>>>(ei, ne);
    k_prep<<<1536, 256>>>(fc1_w, conv1_w, conv2_w, conv3_w, cls1_w, cls2_w);

    k_gcnAmma<<<2048, 256>>>(src);
    k_gcnBC<<<4096, 256, GCNBC_SMEM>>>(gcn1_w, gcn1_b, gcn2_w, gcn2_b);

    k_convmma<64, 4, 2, 224, 32, 48, 96, 3, 64, 0, CW1_OFF>
        <<<dim3(3072, 1), 256, CONV_SMEM>>>(conv1_b);
    k_convmma<128, 8, 1, 320, 64, 24, 48, 2, 128, 1, CW2_OFF>
        <<<dim3(3072, 1), 256, CONV_SMEM>>>(conv2_b);
    k_convmma<128, 8, 1, 384, 128, 12, 24, 1, 256, 0, CW3_OFF>
        <<<dim3(1536, 2), 256, CONV_SMEM>>>(conv3_b);

    k_fc1mma<<<dim3(128, 2), 256, FC1_SMEM>>>();
    k_fc1epi<<<BB * 128 / 256, 256>>>(fc1_b, out_f);
    k_clsmma<128, 1, CWC1_OFF><<<dim3(128, 1), 256>>>(cls1_b, nullptr);
    k_clsmma<210, 2, CWC2_OFF><<<dim3(128, 2), 256>>>(cls2_b, out_x);
}